// round 2
// baseline (speedup 1.0000x reference)
#include <cuda_runtime.h>
#include <cstdint>
#include <cstddef>

// ---------------- problem constants (fixed by the dataset) ----------------
#define N_ENT      100000
#define N_BASES    50
#define N_RELS     401        // 200 + 200 + 1 (r, -r, self)
#define D          128
#define N_EDGES_C  800000
#define N_TRIPLES_C 4096
#define BN_EPS     1e-5f

// ---------------- scratch (device globals; no allocation allowed) ----------
__device__ float g_r0[N_RELS * D];
__device__ float g_r1[N_RELS * D];
__device__ float g_r2[N_RELS * D];
__device__ float g_RW[3 * N_RELS * D];                 // RW[k][t][c]
__device__ float g_XW[(size_t)3 * N_ENT * D];          // XW[k][v][c]  (153.6 MB)
__device__ float g_X1[(size_t)N_ENT * D];              // 51.2 MB
__device__ float g_X2[(size_t)N_ENT * D];              // 51.2 MB
__device__ float g_sums[D];
__device__ float g_sumsq[D];
__device__ float g_scale[D];
__device__ float g_shift[D];

// ---------------- small helpers ----------------
__device__ __forceinline__ unsigned long long pk2(float v) {
    unsigned long long r;
    asm("mov.b64 %0, {%1, %1};" : "=l"(r) : "f"(v));
    return r;
}
__device__ __forceinline__ void fma2(unsigned long long& d,
                                     unsigned long long a,
                                     unsigned long long b) {
    // Blackwell packed fp32x2 FMA (2x FFMA throughput); only reachable via PTX.
    asm("fma.rn.f32x2 %0, %1, %2, %0;" : "+l"(d) : "l"(a), "l"(b));
}
__device__ __forceinline__ void red_add_v4(float* addr, float4 v) {
    asm volatile("red.global.add.v4.f32 [%0], {%1, %2, %3, %4};"
                 :: "l"(addr), "f"(v.x), "f"(v.y), "f"(v.z), "f"(v.w)
                 : "memory");
}

// ---------------- r0 = [coeff@bases ; -(coeff@bases) ; self] ----------------
__global__ void k_r0(const float* __restrict__ coeff,
                     const float* __restrict__ bases,
                     const float* __restrict__ selfr) {
    int b = blockIdx.x;
    int c = threadIdx.x;
    if (b == 200) { g_r0[400 * D + c] = selfr[c]; return; }
    __shared__ float co[N_BASES];
    if (c < N_BASES) co[c] = coeff[b * N_BASES + c];
    __syncthreads();
    float acc = 0.f;
#pragma unroll
    for (int i = 0; i < N_BASES; ++i) acc += co[i] * bases[i * D + c];
    g_r0[b * D + c] = acc;
    g_r0[(200 + b) * D + c] = -acc;
}

// ---------------- RW[k][t][:] = r_in[t] @ W[k] ----------------
__global__ void k_RW(const float* __restrict__ rin, const float* __restrict__ W) {
    int t = blockIdx.x, k = blockIdx.y, c = threadIdx.x;
    __shared__ float rr[D];
    rr[c] = rin[t * D + c];
    __syncthreads();
    const float* Wk = W + k * D * D;
    float acc = 0.f;
#pragma unroll 16
    for (int d = 0; d < D; ++d) acc += rr[d] * Wk[d * D + c];
    g_RW[((size_t)k * N_RELS + t) * D + c] = acc;
}

// ---------------- r_out[t][:] = r_in[t] @ relw ----------------
__global__ void k_rel(const float* __restrict__ rin,
                      const float* __restrict__ relw,
                      float* __restrict__ rout) {
    int t = blockIdx.x, c = threadIdx.x;
    __shared__ float rr[D];
    rr[c] = rin[t * D + c];
    __syncthreads();
    float acc = 0.f;
#pragma unroll 16
    for (int d = 0; d < D; ++d) acc += rr[d] * relw[d * D + c];
    rout[t * D + c] = acc;
}

// ---------------- big GEMM: XW[k] = X @ W[k]  (M=100000, K=128, N=128 x3) ----
// 128x128 block tile, 8x8 register tile per thread, packed f32x2 FMA.
#define BK 32
#define XT_PITCH 132
__global__ __launch_bounds__(256) void k_xw(const float* __restrict__ X,
                                            const float* __restrict__ W) {
    const int k = blockIdx.y;
    const int row0 = blockIdx.x * 128;
    const float* Wk = W + k * D * D;

    __shared__ float xT[BK * XT_PITCH];   // transposed x tile: xT[d][r]
    __shared__ float Wsm[BK * D];         // Wsm[d][c]

    const int tid = threadIdx.x;
    const int tc = tid & 15;              // 16 col-groups x 8 cols = 128
    const int tr = tid >> 4;              // 16 row-groups x 8 rows = 128
    const int lane = tid & 31, warp = tid >> 5;

    unsigned long long acc[8][4];
#pragma unroll
    for (int r = 0; r < 8; ++r)
#pragma unroll
        for (int p = 0; p < 4; ++p) acc[r][p] = 0ull;

    for (int kc = 0; kc < D; kc += BK) {
        // load x chunk transposed: xT[d][r] = X[row0+r][kc+d]
#pragma unroll
        for (int rr = 0; rr < 16; ++rr) {
            int r = warp + rr * 8;
            int grow = row0 + r;
            float v = (grow < N_ENT) ? X[(size_t)grow * D + kc + lane] : 0.f;
            xT[lane * XT_PITCH + r] = v;
        }
        // load W chunk: Wsm[d][c]
#pragma unroll
        for (int i = 0; i < 16; ++i) {
            int idx = tid + i * 256;
            Wsm[idx] = Wk[(kc + (idx >> 7)) * D + (idx & 127)];
        }
        __syncthreads();

#pragma unroll 4
        for (int d = 0; d < BK; ++d) {
            const float4 av0 = *reinterpret_cast<const float4*>(&xT[d * XT_PITCH + tr * 8]);
            const float4 av1 = *reinterpret_cast<const float4*>(&xT[d * XT_PITCH + tr * 8 + 4]);
            const unsigned long long* bp =
                reinterpret_cast<const unsigned long long*>(&Wsm[d * D + tc * 8]);
            unsigned long long b0 = bp[0], b1 = bp[1], b2 = bp[2], b3 = bp[3];
            unsigned long long ap[8] = {pk2(av0.x), pk2(av0.y), pk2(av0.z), pk2(av0.w),
                                        pk2(av1.x), pk2(av1.y), pk2(av1.z), pk2(av1.w)};
#pragma unroll
            for (int r = 0; r < 8; ++r) {
                fma2(acc[r][0], ap[r], b0);
                fma2(acc[r][1], ap[r], b1);
                fma2(acc[r][2], ap[r], b2);
                fma2(acc[r][3], ap[r], b3);
            }
        }
        __syncthreads();
    }

    // epilogue
#pragma unroll
    for (int r = 0; r < 8; ++r) {
        int grow = row0 + tr * 8 + r;
        if (grow < N_ENT) {
            unsigned long long* dst = reinterpret_cast<unsigned long long*>(
                &g_XW[((size_t)k * N_ENT + grow) * D + tc * 8]);
            dst[0] = acc[r][0]; dst[1] = acc[r][1];
            dst[2] = acc[r][2]; dst[3] = acc[r][3];
        }
    }
}

// ---------------- edge scatter: agg[dst] += XW[y][src] - RW[y][type] --------
__global__ void k_edge(const int* __restrict__ ei,
                       const int* __restrict__ et,
                       const int* __restrict__ yv,
                       float* __restrict__ agg) {
    int e = blockIdx.x * 8 + (threadIdx.x >> 5);
    if (e >= N_EDGES_C) return;
    int lane = threadIdx.x & 31;
    int src = __ldg(ei + e);
    int dst = __ldg(ei + N_EDGES_C + e);
    int tt  = __ldg(et + e);
    int cls = __ldg(yv + e);

    const float4 xv = __ldg(reinterpret_cast<const float4*>(
                                g_XW + ((size_t)cls * N_ENT + src) * D) + lane);
    const float4 rv = __ldg(reinterpret_cast<const float4*>(
                                g_RW + ((size_t)cls * N_RELS + tt) * D) + lane);
    float4 v = make_float4(xv.x - rv.x, xv.y - rv.y, xv.z - rv.z, xv.w - rv.w);
    red_add_v4(agg + (size_t)dst * D + lane * 4, v);
}

// ---------------- zero / stats / bn finalize / bn+tanh ----------------
__global__ void k_zero(float* __restrict__ p, int n4) {
    int i = blockIdx.x * blockDim.x + threadIdx.x;
    if (i < n4) reinterpret_cast<float4*>(p)[i] = make_float4(0.f, 0.f, 0.f, 0.f);
}
__global__ void k_zero_stats() {
    int t = threadIdx.x;
    if (t < D) g_sums[t] = 0.f;
    else if (t < 2 * D) g_sumsq[t - D] = 0.f;
}
__global__ void k_stats(const float* __restrict__ agg) {
    int c = threadIdx.x;
    float s = 0.f, s2 = 0.f;
    for (int row = blockIdx.x; row < N_ENT; row += gridDim.x) {
        float v = agg[(size_t)row * D + c];
        s += v; s2 += v * v;
    }
    atomicAdd(&g_sums[c], s);
    atomicAdd(&g_sumsq[c], s2);
}
__global__ void k_finalize(const float* __restrict__ gamma,
                           const float* __restrict__ beta) {
    int c = threadIdx.x;
    float inv_n = 1.0f / (float)N_ENT;
    float mean = g_sums[c] * inv_n;
    float var = fmaxf(g_sumsq[c] * inv_n - mean * mean, 0.f);
    float rs = rsqrtf(var + BN_EPS);
    float sc = rs * gamma[c];
    g_scale[c] = sc;
    g_shift[c] = beta[c] - mean * sc;
}
__global__ void k_bntanh(float* __restrict__ xio) {
    int i = blockIdx.x * blockDim.x + threadIdx.x;      // float4 index
    if (i >= N_ENT * D / 4) return;
    int c4 = (i & 31) * 4;
    float4 v = reinterpret_cast<float4*>(xio)[i];
    v.x = tanhf(v.x * g_scale[c4 + 0] + g_shift[c4 + 0]);
    v.y = tanhf(v.y * g_scale[c4 + 1] + g_shift[c4 + 1]);
    v.z = tanhf(v.z * g_scale[c4 + 2] + g_shift[c4 + 2]);
    v.w = tanhf(v.w * g_scale[c4 + 3] + g_shift[c4 + 3]);
    reinterpret_cast<float4*>(xio)[i] = v;
}

// ---------------- scoring ----------------
__global__ void k_score(const int* __restrict__ trip, float* __restrict__ out) {
    int t = blockIdx.x * 8 + (threadIdx.x >> 5);
    if (t >= N_TRIPLES_C) return;
    int lane = threadIdx.x & 31;
    int h = trip[t * 3], rl = trip[t * 3 + 1], tl = trip[t * 3 + 2];
    float4 hv = *(reinterpret_cast<const float4*>(g_X2 + (size_t)h * D) + lane);
    float4 rv = *(reinterpret_cast<const float4*>(g_r2 + (size_t)rl * D) + lane);
    float4 tv = *(reinterpret_cast<const float4*>(g_X2 + (size_t)tl * D) + lane);
    float p = fabsf(hv.x + rv.x - tv.x) + fabsf(hv.y + rv.y - tv.y) +
              fabsf(hv.z + rv.z - tv.z) + fabsf(hv.w + rv.w - tv.w);
#pragma unroll
    for (int o = 16; o; o >>= 1) p += __shfl_xor_sync(0xffffffffu, p, o);
    if (lane == 0) out[t] = p;
}

// ---------------- host side ----------------
static float* sym_addr_f(const void* sym) {
    void* p = nullptr;
    cudaGetSymbolAddress(&p, sym);
    return reinterpret_cast<float*>(p);
}

extern "C" void kernel_launch(void* const* d_in, const int* in_sizes, int n_in,
                              void* d_out, int out_size) {
    (void)in_sizes; (void)n_in; (void)out_size;
    const float* entity = (const float*)d_in[0];
    const float* bases  = (const float*)d_in[1];
    const float* coeff  = (const float*)d_in[2];
    const float* selfr  = (const float*)d_in[3];
    const float* W1     = (const float*)d_in[4];
    const float* relw1  = (const float*)d_in[5];
    const float* g1     = (const float*)d_in[6];
    const float* b1     = (const float*)d_in[7];
    const float* W2     = (const float*)d_in[8];
    const float* relw2  = (const float*)d_in[9];
    const float* g2     = (const float*)d_in[10];
    const float* b2     = (const float*)d_in[11];
    // d_in[12] = ent_ids (arange; identity gather)
    const int* edge_index = (const int*)d_in[13];
    const int* edge_type  = (const int*)d_in[14];
    const int* yv         = (const int*)d_in[15];
    const int* triples    = (const int*)d_in[16];
    float* out = (float*)d_out;

    float* p_r0 = sym_addr_f(g_r0);
    float* p_r1 = sym_addr_f(g_r1);
    float* p_r2 = sym_addr_f(g_r2);
    float* p_X1 = sym_addr_f(g_X1);
    float* p_X2 = sym_addr_f(g_X2);

    const int n4 = N_ENT * D / 4;          // 3,200,000
    const int zb = n4 / 256;               // 12,500 blocks
    const dim3 gRW(N_RELS, 3);
    const dim3 gXW((N_ENT + 127) / 128, 3);

    // relation tables
    k_r0<<<201, 128>>>(coeff, bases, selfr);

    // ---- layer 1 ----
    k_RW<<<gRW, 128>>>(p_r0, W1);
    k_xw<<<gXW, 256>>>(entity, W1);
    k_zero<<<zb, 256>>>(p_X1, n4);
    k_edge<<<N_EDGES_C / 8, 256>>>(edge_index, edge_type, yv, p_X1);
    k_zero_stats<<<1, 256>>>();
    k_stats<<<512, 128>>>(p_X1);
    k_finalize<<<1, 128>>>(g1, b1);
    k_bntanh<<<zb, 256>>>(p_X1);
    k_rel<<<N_RELS, 128>>>(p_r0, relw1, p_r1);

    // ---- layer 2 ----
    k_RW<<<gRW, 128>>>(p_r1, W2);
    k_xw<<<gXW, 256>>>(p_X1, W2);
    k_zero<<<zb, 256>>>(p_X2, n4);
    k_edge<<<N_EDGES_C / 8, 256>>>(edge_index, edge_type, yv, p_X2);
    k_zero_stats<<<1, 256>>>();
    k_stats<<<512, 128>>>(p_X2);
    k_finalize<<<1, 128>>>(g2, b2);
    k_bntanh<<<zb, 256>>>(p_X2);
    k_rel<<<N_RELS, 128>>>(p_r1, relw2, p_r2);

    // ---- scoring ----
    k_score<<<N_TRIPLES_C / 8, 256>>>(triples, out);
}

// round 4
// speedup vs baseline: 1.3374x; 1.3374x over previous
#include <cuda_runtime.h>
#include <cuda_bf16.h>
#include <cstdint>
#include <cstddef>

// ---------------- problem constants ----------------
#define N_ENT      100000
#define N_RELS     401
#define N_BASES    50
#define D          128
#define N_EDGES_C  800000
#define N_TRIPLES_C 4096
#define BN_EPS     1e-5f
#define M_TILES    782            // ceil(100000/128)

// ---------------- scratch ----------------
__device__ float g_r0[N_RELS * D];
__device__ float g_r1[N_RELS * D];
__device__ float g_r2[N_RELS * D];
__device__ float g_agg3[(size_t)3 * N_ENT * D];        // per-class aggregates (153.6 MB)
__device__ float g_X1[(size_t)N_ENT * D];
__device__ float g_X2[(size_t)N_ENT * D];
__device__ float g_sums[D];
__device__ float g_sumsq[D];
__device__ float g_scale[D];
__device__ float g_shift[D];
__device__ __nv_bfloat16 g_Wh[3 * D * D];              // bf16 hi of W[k], [k][kk][n]
__device__ __nv_bfloat16 g_Wl[3 * D * D];              // bf16 lo residual

// ---------------- helpers ----------------
__device__ __forceinline__ uint32_t smem_u32(const void* p) {
    uint32_t a;
    asm("{ .reg .u64 t; cvta.to.shared.u64 t, %1; cvt.u32.u64 %0, t; }" : "=r"(a) : "l"(p));
    return a;
}
__device__ __forceinline__ void red_add_v4(float* addr, float4 v) {
    asm volatile("red.global.add.v4.f32 [%0], {%1, %2, %3, %4};"
                 :: "l"(addr), "f"(v.x), "f"(v.y), "f"(v.z), "f"(v.w) : "memory");
}
__device__ __forceinline__ uint32_t pkbf(float a, float b) {
    __nv_bfloat162 t = __floats2bfloat162_rn(a, b);
    return *reinterpret_cast<uint32_t*>(&t);
}
__device__ __forceinline__ void ldsm_x4(uint32_t* r, uint32_t addr) {
    asm volatile("ldmatrix.sync.aligned.m8n8.x4.shared.b16 {%0,%1,%2,%3}, [%4];"
                 : "=r"(r[0]), "=r"(r[1]), "=r"(r[2]), "=r"(r[3]) : "r"(addr));
}
__device__ __forceinline__ void ldsm_x4_t(uint32_t* r, uint32_t addr) {
    asm volatile("ldmatrix.sync.aligned.m8n8.x4.trans.shared.b16 {%0,%1,%2,%3}, [%4];"
                 : "=r"(r[0]), "=r"(r[1]), "=r"(r[2]), "=r"(r[3]) : "r"(addr));
}
__device__ __forceinline__ void mma16816(float* c, const uint32_t* a, const uint32_t* b) {
    asm volatile(
        "mma.sync.aligned.m16n8k16.row.col.f32.bf16.bf16.f32 "
        "{%0,%1,%2,%3}, {%4,%5,%6,%7}, {%8,%9}, {%0,%1,%2,%3};"
        : "+f"(c[0]), "+f"(c[1]), "+f"(c[2]), "+f"(c[3])
        : "r"(a[0]), "r"(a[1]), "r"(a[2]), "r"(a[3]), "r"(b[0]), "r"(b[1]));
}

// ---------------- W split prep: g_Wh/g_Wl[k][kk][n] ----------------
__global__ void k_wsplit(const float* __restrict__ W) {
    int k = blockIdx.x;
    for (int idx = threadIdx.x; idx < D * D; idx += blockDim.x) {
        float v = W[k * D * D + idx];
        __nv_bfloat16 h = __float2bfloat16(v);
        __nv_bfloat16 l = __float2bfloat16(v - __bfloat162float(h));
        g_Wh[k * D * D + idx] = h;
        g_Wl[k * D * D + idx] = l;
    }
}

// ---------------- r0 = [coeff@bases ; -(coeff@bases) ; self] ----------------
__global__ void k_r0(const float* __restrict__ coeff,
                     const float* __restrict__ bases,
                     const float* __restrict__ selfr) {
    int b = blockIdx.x, c = threadIdx.x;
    if (b == 200) { g_r0[400 * D + c] = selfr[c]; return; }
    __shared__ float co[N_BASES];
    if (c < N_BASES) co[c] = coeff[b * N_BASES + c];
    __syncthreads();
    float acc = 0.f;
#pragma unroll
    for (int i = 0; i < N_BASES; ++i) acc += co[i] * bases[i * D + c];
    g_r0[b * D + c] = acc;
    g_r0[(200 + b) * D + c] = -acc;
}

// ---------------- r_out = r_in @ relw ----------------
__global__ void k_rel(const float* __restrict__ rin,
                      const float* __restrict__ relw,
                      float* __restrict__ rout) {
    int t = blockIdx.x, c = threadIdx.x;
    __shared__ float rr[D];
    rr[c] = rin[t * D + c];
    __syncthreads();
    float acc = 0.f;
#pragma unroll 16
    for (int d = 0; d < D; ++d) acc += rr[d] * relw[d * D + c];
    rout[t * D + c] = acc;
}

// ---------------- edge scatter: agg3[y][dst] += x[src] - r[type] ----------------
__global__ void k_edge(const int* __restrict__ ei,
                       const int* __restrict__ et,
                       const int* __restrict__ yv,
                       const float* __restrict__ x,
                       const float* __restrict__ rtab) {
    int e = blockIdx.x * 8 + (threadIdx.x >> 5);
    if (e >= N_EDGES_C) return;
    int lane = threadIdx.x & 31;
    int src = __ldg(ei + e);
    int dst = __ldg(ei + N_EDGES_C + e);
    int tt  = __ldg(et + e);
    int cls = __ldg(yv + e);
    const float4 xv = __ldg(reinterpret_cast<const float4*>(x + (size_t)src * D) + lane);
    const float4 rv = __ldg(reinterpret_cast<const float4*>(rtab + (size_t)tt * D) + lane);
    float4 v = make_float4(xv.x - rv.x, xv.y - rv.y, xv.z - rv.z, xv.w - rv.w);
    red_add_v4(g_agg3 + ((size_t)cls * N_ENT + dst) * D + lane * 4, v);
}

// ---------------- GEMM: out = sum_k agg3[k] @ W[k], split-bf16 mma.sync ----------------
#define AP 136                       // SMEM row pitch (bf16 elems) -> 272B, LDSM conflict-free
#define TILE_BYTES (128 * AP * 2)    // 34816
#define SMEM_DYN (4 * TILE_BYTES)    // Ah, Al, Wh, Wl = 139264
__global__ __launch_bounds__(256, 1) void k_gemm(const float* __restrict__ agg3,
                                                 float* __restrict__ outp) {
    extern __shared__ unsigned char sm[];
    __nv_bfloat16* sAh = reinterpret_cast<__nv_bfloat16*>(sm);
    __nv_bfloat16* sAl = reinterpret_cast<__nv_bfloat16*>(sm + TILE_BYTES);
    __nv_bfloat16* sWh = reinterpret_cast<__nv_bfloat16*>(sm + 2 * TILE_BYTES);
    __nv_bfloat16* sWl = reinterpret_cast<__nv_bfloat16*>(sm + 3 * TILE_BYTES);

    const int tid = threadIdx.x, wid = tid >> 5, lane = tid & 31;
    const int row0 = blockIdx.x * 128;
    const int wm = wid >> 1, wn = wid & 1;          // 4x2 warp grid
    const int mbase = wm * 32, nbase = wn * 64;

    const uint32_t uAh = smem_u32(sAh), uAl = smem_u32(sAl);
    const uint32_t uWh = smem_u32(sWh), uWl = smem_u32(sWl);

    float acc[16][4];                               // atom = mt*8 + nt
#pragma unroll
    for (int i = 0; i < 16; ++i)
#pragma unroll
        for (int j = 0; j < 4; ++j) acc[i][j] = 0.f;

    for (int k = 0; k < 3; ++k) {
        __syncthreads();
        // W tiles: 16384 bf16 each, copy as uint4 (8 bf16), repitch to AP
        const uint4* gwh = reinterpret_cast<const uint4*>(g_Wh + k * D * D);
        const uint4* gwl = reinterpret_cast<const uint4*>(g_Wl + k * D * D);
#pragma unroll
        for (int i = 0; i < 8; ++i) {
            int idx = tid + i * 256;                // 2048 uint4
            int r = idx >> 4, c8 = (idx & 15) * 8;
            *reinterpret_cast<uint4*>(sWh + r * AP + c8) = gwh[idx];
            *reinterpret_cast<uint4*>(sWl + r * AP + c8) = gwl[idx];
        }
        // A tile: read fp32, split into hi/lo bf16
#pragma unroll
        for (int i = 0; i < 16; ++i) {
            int e4 = tid + i * 256;                 // 4096 float4
            int r = e4 >> 5, c = (e4 & 31) * 4;
            float4 v = make_float4(0.f, 0.f, 0.f, 0.f);
            int grow = row0 + r;
            if (grow < N_ENT)
                v = *reinterpret_cast<const float4*>(agg3 + ((size_t)k * N_ENT + grow) * D + c);
            float hx = __bfloat162float(__float2bfloat16(v.x));
            float hy = __bfloat162float(__float2bfloat16(v.y));
            float hz = __bfloat162float(__float2bfloat16(v.z));
            float hw = __bfloat162float(__float2bfloat16(v.w));
            *reinterpret_cast<uint2*>(sAh + r * AP + c) = make_uint2(pkbf(hx, hy), pkbf(hz, hw));
            *reinterpret_cast<uint2*>(sAl + r * AP + c) =
                make_uint2(pkbf(v.x - hx, v.y - hy), pkbf(v.z - hz, v.w - hw));
        }
        __syncthreads();

#pragma unroll
        for (int ks = 0; ks < 8; ++ks) {
            const int k0 = ks * 16;
            // A fragments (row-major, ldmatrix x4): lane -> row mbase+mt*16+(lane&15), half (lane>>4)
            uint32_t ah[2][4], al[2][4];
#pragma unroll
            for (int mt = 0; mt < 2; ++mt) {
                int row = mbase + mt * 16 + (lane & 15);
                int col = k0 + (lane >> 4) * 8;
                uint32_t off = (uint32_t)(row * AP + col) * 2;
                ldsm_x4(ah[mt], uAh + off);
                ldsm_x4(al[mt], uAl + off);
            }
            // B fragments (k-major [K][N], ldmatrix x4 trans): covers 2 n-tiles per load
            uint32_t bh[8][2], bl[8][2];
#pragma unroll
            for (int p = 0; p < 4; ++p) {
                int row = k0 + ((lane >> 3) & 1) * 8 + (lane & 7);
                int col = nbase + p * 16 + (lane >> 4) * 8;
                uint32_t off = (uint32_t)(row * AP + col) * 2;
                uint32_t t4[4];
                ldsm_x4_t(t4, uWh + off);
                bh[2 * p][0] = t4[0]; bh[2 * p][1] = t4[1];
                bh[2 * p + 1][0] = t4[2]; bh[2 * p + 1][1] = t4[3];
                ldsm_x4_t(t4, uWl + off);
                bl[2 * p][0] = t4[0]; bl[2 * p][1] = t4[1];
                bl[2 * p + 1][0] = t4[2]; bl[2 * p + 1][1] = t4[3];
            }
            // 48 MMAs: Ah*Wh + Al*Wh + Ah*Wl
#pragma unroll
            for (int mt = 0; mt < 2; ++mt)
#pragma unroll
                for (int nt = 0; nt < 8; ++nt) {
                    mma16816(acc[mt * 8 + nt], ah[mt], bh[nt]);
                    mma16816(acc[mt * 8 + nt], al[mt], bh[nt]);
                    mma16816(acc[mt * 8 + nt], ah[mt], bl[nt]);
                }
        }
    }

    // epilogue: c0,c1 -> row g, cols 2t..2t+1 ; c2,c3 -> row g+8
    const int g = lane >> 2, t2 = (lane & 3) * 2;
#pragma unroll
    for (int mt = 0; mt < 2; ++mt) {
        int r0 = row0 + mbase + mt * 16 + g;
        int r1 = r0 + 8;
#pragma unroll
        for (int nt = 0; nt < 8; ++nt) {
            int col = nbase + nt * 8 + t2;
            if (r0 < N_ENT)
                *reinterpret_cast<float2*>(outp + (size_t)r0 * D + col) =
                    make_float2(acc[mt * 8 + nt][0], acc[mt * 8 + nt][1]);
            if (r1 < N_ENT)
                *reinterpret_cast<float2*>(outp + (size_t)r1 * D + col) =
                    make_float2(acc[mt * 8 + nt][2], acc[mt * 8 + nt][3]);
        }
    }
}

// ---------------- zero / stats / bn ----------------
__global__ void k_zero(float* __restrict__ p, int n4) {
    int i = blockIdx.x * blockDim.x + threadIdx.x;
    if (i < n4) reinterpret_cast<float4*>(p)[i] = make_float4(0.f, 0.f, 0.f, 0.f);
}
__global__ void k_zero_stats() {
    int t = threadIdx.x;
    if (t < D) g_sums[t] = 0.f;
    else if (t < 2 * D) g_sumsq[t - D] = 0.f;
}
__global__ void k_stats(const float* __restrict__ agg) {
    int c = threadIdx.x;
    float s = 0.f, s2 = 0.f;
    for (int row = blockIdx.x; row < N_ENT; row += gridDim.x) {
        float v = agg[(size_t)row * D + c];
        s += v; s2 += v * v;
    }
    atomicAdd(&g_sums[c], s);
    atomicAdd(&g_sumsq[c], s2);
}
__global__ void k_finalize(const float* __restrict__ gamma,
                           const float* __restrict__ beta) {
    int c = threadIdx.x;
    float inv_n = 1.0f / (float)N_ENT;
    float mean = g_sums[c] * inv_n;
    float var = fmaxf(g_sumsq[c] * inv_n - mean * mean, 0.f);
    float rs = rsqrtf(var + BN_EPS);
    float sc = rs * gamma[c];
    g_scale[c] = sc;
    g_shift[c] = beta[c] - mean * sc;
}
__global__ void k_bntanh(float* __restrict__ xio) {
    int i = blockIdx.x * blockDim.x + threadIdx.x;
    if (i >= N_ENT * D / 4) return;
    int c4 = (i & 31) * 4;
    float4 v = reinterpret_cast<float4*>(xio)[i];
    v.x = tanhf(v.x * g_scale[c4 + 0] + g_shift[c4 + 0]);
    v.y = tanhf(v.y * g_scale[c4 + 1] + g_shift[c4 + 1]);
    v.z = tanhf(v.z * g_scale[c4 + 2] + g_shift[c4 + 2]);
    v.w = tanhf(v.w * g_scale[c4 + 3] + g_shift[c4 + 3]);
    reinterpret_cast<float4*>(xio)[i] = v;
}

// ---------------- scoring ----------------
__global__ void k_score(const int* __restrict__ trip, float* __restrict__ out) {
    int t = blockIdx.x * 8 + (threadIdx.x >> 5);
    if (t >= N_TRIPLES_C) return;
    int lane = threadIdx.x & 31;
    int h = trip[t * 3], rl = trip[t * 3 + 1], tl = trip[t * 3 + 2];
    float4 hv = *(reinterpret_cast<const float4*>(g_X2 + (size_t)h * D) + lane);
    float4 rv = *(reinterpret_cast<const float4*>(g_r2 + (size_t)rl * D) + lane);
    float4 tv = *(reinterpret_cast<const float4*>(g_X2 + (size_t)tl * D) + lane);
    float p = fabsf(hv.x + rv.x - tv.x) + fabsf(hv.y + rv.y - tv.y) +
              fabsf(hv.z + rv.z - tv.z) + fabsf(hv.w + rv.w - tv.w);
#pragma unroll
    for (int o = 16; o; o >>= 1) p += __shfl_xor_sync(0xffffffffu, p, o);
    if (lane == 0) out[t] = p;
}

// ---------------- host side ----------------
static float* sym_addr_f(const void* sym) {
    void* p = nullptr;
    cudaGetSymbolAddress(&p, sym);
    return reinterpret_cast<float*>(p);
}

extern "C" void kernel_launch(void* const* d_in, const int* in_sizes, int n_in,
                              void* d_out, int out_size) {
    (void)in_sizes; (void)n_in; (void)out_size;
    const float* entity = (const float*)d_in[0];
    const float* bases  = (const float*)d_in[1];
    const float* coeff  = (const float*)d_in[2];
    const float* selfr  = (const float*)d_in[3];
    const float* W1     = (const float*)d_in[4];
    const float* relw1  = (const float*)d_in[5];
    const float* g1     = (const float*)d_in[6];
    const float* b1     = (const float*)d_in[7];
    const float* W2     = (const float*)d_in[8];
    const float* relw2  = (const float*)d_in[9];
    const float* g2     = (const float*)d_in[10];
    const float* b2     = (const float*)d_in[11];
    const int* edge_index = (const int*)d_in[13];
    const int* edge_type  = (const int*)d_in[14];
    const int* yv         = (const int*)d_in[15];
    const int* triples    = (const int*)d_in[16];
    float* out = (float*)d_out;

    float* p_r0 = sym_addr_f(g_r0);
    float* p_r1 = sym_addr_f(g_r1);
    float* p_r2 = sym_addr_f(g_r2);
    float* p_agg = sym_addr_f(g_agg3);
    float* p_X1 = sym_addr_f(g_X1);
    float* p_X2 = sym_addr_f(g_X2);

    cudaFuncSetAttribute(k_gemm, cudaFuncAttributeMaxDynamicSharedMemorySize, SMEM_DYN);

    const int n4a = 3 * N_ENT * D / 4;      // 9.6M float4 (agg3)
    const int zba = (n4a + 255) / 256;

    k_r0<<<201, 128>>>(coeff, bases, selfr);

    // ---- layer 1 ----
    k_wsplit<<<3, 256>>>(W1);
    k_zero<<<zba, 256>>>(p_agg, n4a);
    k_edge<<<N_EDGES_C / 8, 256>>>(edge_index, edge_type, yv, entity, p_r0);
    k_gemm<<<M_TILES, 256, SMEM_DYN>>>(p_agg, p_X1);
    k_zero_stats<<<1, 256>>>();
    k_stats<<<512, 128>>>(p_X1);
    k_finalize<<<1, 128>>>(g1, b1);
    k_bntanh<<<N_ENT * D / 4 / 256, 256>>>(p_X1);
    k_rel<<<N_RELS, 128>>>(p_r0, relw1, p_r1);

    // ---- layer 2 ----
    k_wsplit<<<3, 256>>>(W2);
    k_zero<<<zba, 256>>>(p_agg, n4a);
    k_edge<<<N_EDGES_C / 8, 256>>>(edge_index, edge_type, yv, p_X1, p_r1);
    k_gemm<<<M_TILES, 256, SMEM_DYN>>>(p_agg, p_X2);
    k_zero_stats<<<1, 256>>>();
    k_stats<<<512, 128>>>(p_X2);
    k_finalize<<<1, 128>>>(g2, b2);
    k_bntanh<<<N_ENT * D / 4 / 256, 256>>>(p_X2);
    k_rel<<<N_RELS, 128>>>(p_r1, relw2, p_r2);

    // ---- scoring ----
    k_score<<<N_TRIPLES_C / 8, 256>>>(triples, out);
}

// round 5
// speedup vs baseline: 1.5454x; 1.1555x over previous
#include <cuda_runtime.h>
#include <cuda_bf16.h>
#include <cstdint>
#include <cstddef>

// ---------------- problem constants ----------------
#define N_ENT      100000
#define N_RELS     401
#define N_BASES    50
#define D          128
#define N_EDGES_C  800000
#define N_TRIPLES_C 4096
#define BN_EPS     1e-5f
#define SCAN_BLKS  98             // 98 * 1024 >= 100000

// ---------------- scratch ----------------
__device__ float g_r0[N_RELS * D];
__device__ float g_r1[N_RELS * D];
__device__ float g_r2[N_RELS * D];
__device__ float g_agg3[(size_t)3 * N_ENT * D];        // per-class aggregates (153.6 MB)
__device__ float g_X1[(size_t)N_ENT * D];
__device__ float g_X2[(size_t)N_ENT * D];
__device__ float g_sums[D];
__device__ float g_sumsq[D];
__device__ float g_scale[D];
__device__ float g_shift[D];
__device__ __nv_bfloat16 g_Wh[3 * D * D];
__device__ __nv_bfloat16 g_Wl[3 * D * D];
// CSR
__device__ int g_deg[N_ENT];
__device__ int g_rs[N_ENT];            // row starts (exclusive scan of deg)
__device__ int g_cur[N_ENT];
__device__ int g_bsum[SCAN_BLKS];
__device__ int g_boff[SCAN_BLKS];
__device__ int g_esrc[N_EDGES_C];
__device__ int g_emeta[N_EDGES_C];     // et | (y<<16)

// ---------------- helpers ----------------
__device__ __forceinline__ uint32_t smem_u32(const void* p) {
    uint32_t a;
    asm("{ .reg .u64 t; cvta.to.shared.u64 t, %1; cvt.u32.u64 %0, t; }" : "=r"(a) : "l"(p));
    return a;
}
__device__ __forceinline__ uint32_t pkbf(float a, float b) {
    __nv_bfloat162 t = __floats2bfloat162_rn(a, b);
    return *reinterpret_cast<uint32_t*>(&t);
}
__device__ __forceinline__ void ldsm_x4(uint32_t* r, uint32_t addr) {
    asm volatile("ldmatrix.sync.aligned.m8n8.x4.shared.b16 {%0,%1,%2,%3}, [%4];"
                 : "=r"(r[0]), "=r"(r[1]), "=r"(r[2]), "=r"(r[3]) : "r"(addr));
}
__device__ __forceinline__ void ldsm_x4_t(uint32_t* r, uint32_t addr) {
    asm volatile("ldmatrix.sync.aligned.m8n8.x4.trans.shared.b16 {%0,%1,%2,%3}, [%4];"
                 : "=r"(r[0]), "=r"(r[1]), "=r"(r[2]), "=r"(r[3]) : "r"(addr));
}
__device__ __forceinline__ void mma16816(float* c, const uint32_t* a, const uint32_t* b) {
    asm volatile(
        "mma.sync.aligned.m16n8k16.row.col.f32.bf16.bf16.f32 "
        "{%0,%1,%2,%3}, {%4,%5,%6,%7}, {%8,%9}, {%0,%1,%2,%3};"
        : "+f"(c[0]), "+f"(c[1]), "+f"(c[2]), "+f"(c[3])
        : "r"(a[0]), "r"(a[1]), "r"(a[2]), "r"(a[3]), "r"(b[0]), "r"(b[1]));
}

// ================= CSR build =================
__global__ void k_zero_i(int* p, int n) {
    int i = blockIdx.x * blockDim.x + threadIdx.x;
    if (i < n) p[i] = 0;
}
__global__ void k_hist(const int* __restrict__ ei) {
    int e = blockIdx.x * blockDim.x + threadIdx.x;
    if (e < N_EDGES_C) atomicAdd(&g_deg[ei[N_EDGES_C + e]], 1);
}
__global__ void k_scan1() {
    __shared__ int ts[256];
    int b = blockIdx.x, t = threadIdx.x;
    int base = b * 1024 + t * 4;
    int v[4];
#pragma unroll
    for (int j = 0; j < 4; ++j)
        v[j] = (base + j < N_ENT) ? g_deg[base + j] : 0;
    int s = v[0] + v[1] + v[2] + v[3];
    ts[t] = s;
    __syncthreads();
    for (int off = 1; off < 256; off <<= 1) {
        int x = (t >= off) ? ts[t - off] : 0;
        __syncthreads();
        ts[t] += x;
        __syncthreads();
    }
    int excl = ts[t] - s;
    if (t == 255) g_bsum[b] = ts[255];
#pragma unroll
    for (int j = 0; j < 4; ++j) {
        if (base + j < N_ENT) g_rs[base + j] = excl;
        excl += v[j];
    }
}
__global__ void k_scan2() {
    if (threadIdx.x == 0) {
        int acc = 0;
        for (int i = 0; i < SCAN_BLKS; ++i) { g_boff[i] = acc; acc += g_bsum[i]; }
    }
}
__global__ void k_scan3() {
    int i = blockIdx.x * blockDim.x + threadIdx.x;
    if (i < N_ENT) {
        int v = g_rs[i] + g_boff[i >> 10];
        g_rs[i] = v;
        g_cur[i] = v;
    }
}
__global__ void k_perm(const int* __restrict__ ei,
                       const int* __restrict__ et,
                       const int* __restrict__ yv) {
    int e = blockIdx.x * blockDim.x + threadIdx.x;
    if (e >= N_EDGES_C) return;
    int dst = ei[N_EDGES_C + e];
    int pos = atomicAdd(&g_cur[dst], 1);
    g_esrc[pos] = ei[e];
    g_emeta[pos] = et[e] | (yv[e] << 16);
}

// ================= per-dst aggregation (no atomics) =================
__global__ __launch_bounds__(256) void k_aggr(const float* __restrict__ x,
                                              const float* __restrict__ rtab) {
    int d = blockIdx.x * 8 + (threadIdx.x >> 5);
    if (d >= N_ENT) return;
    int lane = threadIdx.x & 31;
    int start = g_rs[d];
    int end = start + g_deg[d];
    float4 a0 = make_float4(0.f, 0.f, 0.f, 0.f), a1 = a0, a2 = a0;
    for (int i = start; i < end; ++i) {
        int src = __ldg(g_esrc + i);
        int m = __ldg(g_emeta + i);
        int tt = m & 0xFFFF, y = m >> 16;
        float4 xv = __ldg(reinterpret_cast<const float4*>(x + (size_t)src * D) + lane);
        float4 rv = __ldg(reinterpret_cast<const float4*>(rtab + (size_t)tt * D) + lane);
        float4 v = make_float4(xv.x - rv.x, xv.y - rv.y, xv.z - rv.z, xv.w - rv.w);
        if (y == 0)      { a0.x += v.x; a0.y += v.y; a0.z += v.z; a0.w += v.w; }
        else if (y == 1) { a1.x += v.x; a1.y += v.y; a1.z += v.z; a1.w += v.w; }
        else             { a2.x += v.x; a2.y += v.y; a2.z += v.z; a2.w += v.w; }
    }
    float4* o0 = reinterpret_cast<float4*>(g_agg3 + (size_t)d * D) + lane;
    float4* o1 = reinterpret_cast<float4*>(g_agg3 + ((size_t)N_ENT + d) * D) + lane;
    float4* o2 = reinterpret_cast<float4*>(g_agg3 + ((size_t)2 * N_ENT + d) * D) + lane;
    *o0 = a0; *o1 = a1; *o2 = a2;
}

// ================= W split prep =================
__global__ void k_wsplit(const float* __restrict__ W) {
    int k = blockIdx.x;
    for (int idx = threadIdx.x; idx < D * D; idx += blockDim.x) {
        float v = W[k * D * D + idx];
        __nv_bfloat16 h = __float2bfloat16(v);
        __nv_bfloat16 l = __float2bfloat16(v - __bfloat162float(h));
        g_Wh[k * D * D + idx] = h;
        g_Wl[k * D * D + idx] = l;
    }
}

// ================= r0 / rel =================
__global__ void k_r0(const float* __restrict__ coeff,
                     const float* __restrict__ bases,
                     const float* __restrict__ selfr) {
    int b = blockIdx.x, c = threadIdx.x;
    if (b == 200) { g_r0[400 * D + c] = selfr[c]; return; }
    __shared__ float co[N_BASES];
    if (c < N_BASES) co[c] = coeff[b * N_BASES + c];
    __syncthreads();
    float acc = 0.f;
#pragma unroll
    for (int i = 0; i < N_BASES; ++i) acc += co[i] * bases[i * D + c];
    g_r0[b * D + c] = acc;
    g_r0[(200 + b) * D + c] = -acc;
}
__global__ void k_rel(const float* __restrict__ rin,
                      const float* __restrict__ relw,
                      float* __restrict__ rout) {
    int t = blockIdx.x, c = threadIdx.x;
    __shared__ float rr[D];
    rr[c] = rin[t * D + c];
    __syncthreads();
    float acc = 0.f;
#pragma unroll 16
    for (int d = 0; d < D; ++d) acc += rr[d] * relw[d * D + c];
    rout[t * D + c] = acc;
}

// ================= GEMM: out = sum_k agg3[k] @ W[k] (M-tile 64, 2 CTA/SM) ====
#define AP 136
#define A_TILE_B (64 * AP * 2)          // 17408
#define W_TILE_B (128 * AP * 2)         // 34816
#define SMEM_DYN (2 * A_TILE_B + 2 * W_TILE_B)   // 104448
#define GEMM_BLKS 1563                  // ceil(100000/64)
__global__ __launch_bounds__(256, 2) void k_gemm(const float* __restrict__ agg3,
                                                 float* __restrict__ outp) {
    extern __shared__ unsigned char sm[];
    __nv_bfloat16* sAh = reinterpret_cast<__nv_bfloat16*>(sm);
    __nv_bfloat16* sAl = reinterpret_cast<__nv_bfloat16*>(sm + A_TILE_B);
    __nv_bfloat16* sWh = reinterpret_cast<__nv_bfloat16*>(sm + 2 * A_TILE_B);
    __nv_bfloat16* sWl = reinterpret_cast<__nv_bfloat16*>(sm + 2 * A_TILE_B + W_TILE_B);

    const int tid = threadIdx.x, wid = tid >> 5, lane = tid & 31;
    const int row0 = blockIdx.x * 64;
    const int wm = wid >> 1, wn = wid & 1;      // 4x2 warp grid
    const int mbase = wm * 16, nbase = wn * 64;

    const uint32_t uAh = smem_u32(sAh), uAl = smem_u32(sAl);
    const uint32_t uWh = smem_u32(sWh), uWl = smem_u32(sWl);

    float acc[8][4];
#pragma unroll
    for (int i = 0; i < 8; ++i)
#pragma unroll
        for (int j = 0; j < 4; ++j) acc[i][j] = 0.f;

    for (int k = 0; k < 3; ++k) {
        __syncthreads();
        // W tiles (16384 bf16 each = 2048 uint4), repitch to AP
        const uint4* gwh = reinterpret_cast<const uint4*>(g_Wh + k * D * D);
        const uint4* gwl = reinterpret_cast<const uint4*>(g_Wl + k * D * D);
#pragma unroll
        for (int i = 0; i < 8; ++i) {
            int idx = tid + i * 256;
            int r = idx >> 4, c8 = (idx & 15) * 8;
            *reinterpret_cast<uint4*>(sWh + r * AP + c8) = gwh[idx];
            *reinterpret_cast<uint4*>(sWl + r * AP + c8) = gwl[idx];
        }
        // A tile: 64 x 128 fp32 = 2048 float4, split into hi/lo bf16
#pragma unroll
        for (int i = 0; i < 8; ++i) {
            int e4 = tid + i * 256;
            int r = e4 >> 5, c = (e4 & 31) * 4;
            float4 v = make_float4(0.f, 0.f, 0.f, 0.f);
            int grow = row0 + r;
            if (grow < N_ENT)
                v = *reinterpret_cast<const float4*>(agg3 + ((size_t)k * N_ENT + grow) * D + c);
            float hx = __bfloat162float(__float2bfloat16(v.x));
            float hy = __bfloat162float(__float2bfloat16(v.y));
            float hz = __bfloat162float(__float2bfloat16(v.z));
            float hw = __bfloat162float(__float2bfloat16(v.w));
            *reinterpret_cast<uint2*>(sAh + r * AP + c) = make_uint2(pkbf(hx, hy), pkbf(hz, hw));
            *reinterpret_cast<uint2*>(sAl + r * AP + c) =
                make_uint2(pkbf(v.x - hx, v.y - hy), pkbf(v.z - hz, v.w - hw));
        }
        __syncthreads();

#pragma unroll
        for (int ks = 0; ks < 8; ++ks) {
            const int k0 = ks * 16;
            uint32_t ah[4], al[4];
            {
                int row = mbase + (lane & 15);
                int col = k0 + (lane >> 4) * 8;
                uint32_t off = (uint32_t)(row * AP + col) * 2;
                ldsm_x4(ah, uAh + off);
                ldsm_x4(al, uAl + off);
            }
            uint32_t bh[8][2], bl[8][2];
#pragma unroll
            for (int p = 0; p < 4; ++p) {
                int row = k0 + ((lane >> 3) & 1) * 8 + (lane & 7);
                int col = nbase + p * 16 + (lane >> 4) * 8;
                uint32_t off = (uint32_t)(row * AP + col) * 2;
                uint32_t t4[4];
                ldsm_x4_t(t4, uWh + off);
                bh[2 * p][0] = t4[0]; bh[2 * p][1] = t4[1];
                bh[2 * p + 1][0] = t4[2]; bh[2 * p + 1][1] = t4[3];
                ldsm_x4_t(t4, uWl + off);
                bl[2 * p][0] = t4[0]; bl[2 * p][1] = t4[1];
                bl[2 * p + 1][0] = t4[2]; bl[2 * p + 1][1] = t4[3];
            }
#pragma unroll
            for (int nt = 0; nt < 8; ++nt) {
                mma16816(acc[nt], ah, bh[nt]);
                mma16816(acc[nt], al, bh[nt]);
                mma16816(acc[nt], ah, bl[nt]);
            }
        }
    }

    const int g = lane >> 2, t2 = (lane & 3) * 2;
    int r0 = row0 + mbase + g;
    int r1 = r0 + 8;
#pragma unroll
    for (int nt = 0; nt < 8; ++nt) {
        int col = nbase + nt * 8 + t2;
        if (r0 < N_ENT)
            *reinterpret_cast<float2*>(outp + (size_t)r0 * D + col) =
                make_float2(acc[nt][0], acc[nt][1]);
        if (r1 < N_ENT)
            *reinterpret_cast<float2*>(outp + (size_t)r1 * D + col) =
                make_float2(acc[nt][2], acc[nt][3]);
    }
}

// ================= stats / bn =================
__global__ void k_zero_stats() {
    int t = threadIdx.x;
    if (t < D) g_sums[t] = 0.f;
    else if (t < 2 * D) g_sumsq[t - D] = 0.f;
}
__global__ void k_stats(const float* __restrict__ agg) {
    int c = threadIdx.x;
    float s = 0.f, s2 = 0.f;
    for (int row = blockIdx.x; row < N_ENT; row += gridDim.x) {
        float v = agg[(size_t)row * D + c];
        s += v; s2 += v * v;
    }
    atomicAdd(&g_sums[c], s);
    atomicAdd(&g_sumsq[c], s2);
}
__global__ void k_finalize(const float* __restrict__ gamma,
                           const float* __restrict__ beta) {
    int c = threadIdx.x;
    float inv_n = 1.0f / (float)N_ENT;
    float mean = g_sums[c] * inv_n;
    float var = fmaxf(g_sumsq[c] * inv_n - mean * mean, 0.f);
    float rs = rsqrtf(var + BN_EPS);
    float sc = rs * gamma[c];
    g_scale[c] = sc;
    g_shift[c] = beta[c] - mean * sc;
}
__global__ void k_bntanh(float* __restrict__ xio) {
    int i = blockIdx.x * blockDim.x + threadIdx.x;
    if (i >= N_ENT * D / 4) return;
    int c4 = (i & 31) * 4;
    float4 v = reinterpret_cast<float4*>(xio)[i];
    v.x = tanhf(v.x * g_scale[c4 + 0] + g_shift[c4 + 0]);
    v.y = tanhf(v.y * g_scale[c4 + 1] + g_shift[c4 + 1]);
    v.z = tanhf(v.z * g_scale[c4 + 2] + g_shift[c4 + 2]);
    v.w = tanhf(v.w * g_scale[c4 + 3] + g_shift[c4 + 3]);
    reinterpret_cast<float4*>(xio)[i] = v;
}

// ================= scoring =================
__global__ void k_score(const int* __restrict__ trip, float* __restrict__ out) {
    int t = blockIdx.x * 8 + (threadIdx.x >> 5);
    if (t >= N_TRIPLES_C) return;
    int lane = threadIdx.x & 31;
    int h = trip[t * 3], rl = trip[t * 3 + 1], tl = trip[t * 3 + 2];
    float4 hv = *(reinterpret_cast<const float4*>(g_X2 + (size_t)h * D) + lane);
    float4 rv = *(reinterpret_cast<const float4*>(g_r2 + (size_t)rl * D) + lane);
    float4 tv = *(reinterpret_cast<const float4*>(g_X2 + (size_t)tl * D) + lane);
    float p = fabsf(hv.x + rv.x - tv.x) + fabsf(hv.y + rv.y - tv.y) +
              fabsf(hv.z + rv.z - tv.z) + fabsf(hv.w + rv.w - tv.w);
#pragma unroll
    for (int o = 16; o; o >>= 1) p += __shfl_xor_sync(0xffffffffu, p, o);
    if (lane == 0) out[t] = p;
}

// ================= host side =================
static float* sym_addr_f(const void* sym) {
    void* p = nullptr;
    cudaGetSymbolAddress(&p, sym);
    return reinterpret_cast<float*>(p);
}
static int* sym_addr_i(const void* sym) {
    void* p = nullptr;
    cudaGetSymbolAddress(&p, sym);
    return reinterpret_cast<int*>(p);
}

extern "C" void kernel_launch(void* const* d_in, const int* in_sizes, int n_in,
                              void* d_out, int out_size) {
    (void)in_sizes; (void)n_in; (void)out_size;
    const float* entity = (const float*)d_in[0];
    const float* bases  = (const float*)d_in[1];
    const float* coeff  = (const float*)d_in[2];
    const float* selfr  = (const float*)d_in[3];
    const float* W1     = (const float*)d_in[4];
    const float* relw1  = (const float*)d_in[5];
    const float* g1     = (const float*)d_in[6];
    const float* b1     = (const float*)d_in[7];
    const float* W2     = (const float*)d_in[8];
    const float* relw2  = (const float*)d_in[9];
    const float* g2     = (const float*)d_in[10];
    const float* b2     = (const float*)d_in[11];
    const int* edge_index = (const int*)d_in[13];
    const int* edge_type  = (const int*)d_in[14];
    const int* yv         = (const int*)d_in[15];
    const int* triples    = (const int*)d_in[16];
    float* out = (float*)d_out;

    float* p_r0 = sym_addr_f(g_r0);
    float* p_r1 = sym_addr_f(g_r1);
    float* p_r2 = sym_addr_f(g_r2);
    float* p_agg = sym_addr_f(g_agg3);
    float* p_X1 = sym_addr_f(g_X1);
    float* p_X2 = sym_addr_f(g_X2);
    int* p_deg = sym_addr_i(g_deg);

    cudaFuncSetAttribute(k_gemm, cudaFuncAttributeMaxDynamicSharedMemorySize, SMEM_DYN);

    // ---- CSR build (once; serves both layers) ----
    k_zero_i<<<(N_ENT + 255) / 256, 256>>>(p_deg, N_ENT);
    k_hist<<<(N_EDGES_C + 255) / 256, 256>>>(edge_index);
    k_scan1<<<SCAN_BLKS, 256>>>();
    k_scan2<<<1, 32>>>();
    k_scan3<<<(N_ENT + 255) / 256, 256>>>();
    k_perm<<<(N_EDGES_C + 255) / 256, 256>>>(edge_index, edge_type, yv);

    k_r0<<<201, 128>>>(coeff, bases, selfr);

    // ---- layer 1 ----
    k_wsplit<<<3, 256>>>(W1);
    k_aggr<<<N_ENT / 8, 256>>>(entity, p_r0);
    k_gemm<<<GEMM_BLKS, 256, SMEM_DYN>>>(p_agg, p_X1);
    k_zero_stats<<<1, 256>>>();
    k_stats<<<512, 128>>>(p_X1);
    k_finalize<<<1, 128>>>(g1, b1);
    k_bntanh<<<N_ENT * D / 4 / 256, 256>>>(p_X1);
    k_rel<<<N_RELS, 128>>>(p_r0, relw1, p_r1);

    // ---- layer 2 ----
    k_wsplit<<<3, 256>>>(W2);
    k_aggr<<<N_ENT / 8, 256>>>(p_X1, p_r1);
    k_gemm<<<GEMM_BLKS, 256, SMEM_DYN>>>(p_agg, p_X2);
    k_zero_stats<<<1, 256>>>();
    k_stats<<<512, 128>>>(p_X2);
    k_finalize<<<1, 128>>>(g2, b2);
    k_bntanh<<<N_ENT * D / 4 / 256, 256>>>(p_X2);
    k_rel<<<N_RELS, 128>>>(p_r1, relw2, p_r2);

    // ---- scoring ----
    k_score<<<N_TRIPLES_C / 8, 256>>>(triples, out);
}

// round 6
// speedup vs baseline: 2.2696x; 1.4686x over previous
#include <cuda_runtime.h>
#include <cuda_fp16.h>
#include <cstdint>
#include <cstddef>

// ---------------- problem constants ----------------
#define N_ENT      100000
#define N_RELS     401
#define N_BASES    50
#define D          128
#define N_EDGES_C  800000
#define N_TRIPLES_C 4096
#define BN_EPS     1e-5f
#define SCAN_BLKS  98             // 98 * 1024 >= 100000

// ---------------- scratch ----------------
__device__ float g_r0[N_RELS * D];
__device__ float g_r1[N_RELS * D];
__device__ float g_r2[N_RELS * D];
__device__ float g_agg3[(size_t)3 * N_ENT * D];        // per-class aggregates (153.6 MB)
__device__ float g_X1[(size_t)N_ENT * D];
__device__ float g_X2[(size_t)N_ENT * D];
__device__ float g_sums[D];
__device__ float g_sumsq[D];
__device__ float g_scale[D];
__device__ float g_shift[D];
__device__ __half g_Wh[3 * D * D];                     // fp16 W[k], [k][kk][n]
// CSR
__device__ int g_deg[N_ENT];
__device__ int g_rs[N_ENT];
__device__ int g_cur[N_ENT];
__device__ int g_bsum[SCAN_BLKS];
__device__ int g_boff[SCAN_BLKS];
__device__ int g_esrc[N_EDGES_C];
__device__ int g_emeta[N_EDGES_C];     // et | (y<<16)

// ---------------- helpers ----------------
__device__ __forceinline__ uint32_t smem_u32(const void* p) {
    uint32_t a;
    asm("{ .reg .u64 t; cvta.to.shared.u64 t, %1; cvt.u32.u64 %0, t; }" : "=r"(a) : "l"(p));
    return a;
}
__device__ __forceinline__ uint32_t pkh(float a, float b) {
    __half2 t = __floats2half2_rn(a, b);
    return *reinterpret_cast<uint32_t*>(&t);
}
__device__ __forceinline__ void ldsm_x4(uint32_t* r, uint32_t addr) {
    asm volatile("ldmatrix.sync.aligned.m8n8.x4.shared.b16 {%0,%1,%2,%3}, [%4];"
                 : "=r"(r[0]), "=r"(r[1]), "=r"(r[2]), "=r"(r[3]) : "r"(addr));
}
__device__ __forceinline__ void ldsm_x4_t(uint32_t* r, uint32_t addr) {
    asm volatile("ldmatrix.sync.aligned.m8n8.x4.trans.shared.b16 {%0,%1,%2,%3}, [%4];"
                 : "=r"(r[0]), "=r"(r[1]), "=r"(r[2]), "=r"(r[3]) : "r"(addr));
}
__device__ __forceinline__ void mma16816(float* c, const uint32_t* a, const uint32_t* b) {
    asm volatile(
        "mma.sync.aligned.m16n8k16.row.col.f32.f16.f16.f32 "
        "{%0,%1,%2,%3}, {%4,%5,%6,%7}, {%8,%9}, {%0,%1,%2,%3};"
        : "+f"(c[0]), "+f"(c[1]), "+f"(c[2]), "+f"(c[3])
        : "r"(a[0]), "r"(a[1]), "r"(a[2]), "r"(a[3]), "r"(b[0]), "r"(b[1]));
}

// ================= CSR build =================
__global__ void k_zero_i(int* p, int n) {
    int i = blockIdx.x * blockDim.x + threadIdx.x;
    if (i < n) p[i] = 0;
}
__global__ void k_hist(const int* __restrict__ ei) {
    int e = blockIdx.x * blockDim.x + threadIdx.x;
    if (e < N_EDGES_C) atomicAdd(&g_deg[ei[N_EDGES_C + e]], 1);
}
__global__ void k_scan1() {
    __shared__ int ts[256];
    int b = blockIdx.x, t = threadIdx.x;
    int base = b * 1024 + t * 4;
    int v[4];
#pragma unroll
    for (int j = 0; j < 4; ++j)
        v[j] = (base + j < N_ENT) ? g_deg[base + j] : 0;
    int s = v[0] + v[1] + v[2] + v[3];
    ts[t] = s;
    __syncthreads();
    for (int off = 1; off < 256; off <<= 1) {
        int x = (t >= off) ? ts[t - off] : 0;
        __syncthreads();
        ts[t] += x;
        __syncthreads();
    }
    int excl = ts[t] - s;
    if (t == 255) g_bsum[b] = ts[255];
#pragma unroll
    for (int j = 0; j < 4; ++j) {
        if (base + j < N_ENT) g_rs[base + j] = excl;
        excl += v[j];
    }
}
__global__ void k_scan2() {
    __shared__ int ts[128];
    int t = threadIdx.x;
    int v = (t < SCAN_BLKS) ? g_bsum[t] : 0;
    ts[t] = v;
    __syncthreads();
    for (int off = 1; off < 128; off <<= 1) {
        int x = (t >= off) ? ts[t - off] : 0;
        __syncthreads();
        ts[t] += x;
        __syncthreads();
    }
    if (t < SCAN_BLKS) g_boff[t] = ts[t] - v;
}
__global__ void k_scan3() {
    int i = blockIdx.x * blockDim.x + threadIdx.x;
    if (i < N_ENT) {
        int v = g_rs[i] + g_boff[i >> 10];
        g_rs[i] = v;
        g_cur[i] = v;
    }
}
__global__ void k_perm(const int* __restrict__ ei,
                       const int* __restrict__ et,
                       const int* __restrict__ yv) {
    int e = blockIdx.x * blockDim.x + threadIdx.x;
    if (e >= N_EDGES_C) return;
    int dst = ei[N_EDGES_C + e];
    int pos = atomicAdd(&g_cur[dst], 1);
    g_esrc[pos] = ei[e];
    g_emeta[pos] = et[e] | (yv[e] << 16);
}

// ================= per-dst aggregation (no atomics) =================
__global__ __launch_bounds__(256) void k_aggr(const float* __restrict__ x,
                                              const float* __restrict__ rtab) {
    int d = blockIdx.x * 8 + (threadIdx.x >> 5);
    if (d >= N_ENT) return;
    int lane = threadIdx.x & 31;
    int start = g_rs[d];
    int end = start + g_deg[d];
    float4 a0 = make_float4(0.f, 0.f, 0.f, 0.f), a1 = a0, a2 = a0;
    for (int i = start; i < end; ++i) {
        int src = __ldg(g_esrc + i);
        int m = __ldg(g_emeta + i);
        int tt = m & 0xFFFF, y = m >> 16;
        float4 xv = __ldg(reinterpret_cast<const float4*>(x + (size_t)src * D) + lane);
        float4 rv = __ldg(reinterpret_cast<const float4*>(rtab + (size_t)tt * D) + lane);
        float4 v = make_float4(xv.x - rv.x, xv.y - rv.y, xv.z - rv.z, xv.w - rv.w);
        if (y == 0)      { a0.x += v.x; a0.y += v.y; a0.z += v.z; a0.w += v.w; }
        else if (y == 1) { a1.x += v.x; a1.y += v.y; a1.z += v.z; a1.w += v.w; }
        else             { a2.x += v.x; a2.y += v.y; a2.z += v.z; a2.w += v.w; }
    }
    float4* o0 = reinterpret_cast<float4*>(g_agg3 + (size_t)d * D) + lane;
    float4* o1 = reinterpret_cast<float4*>(g_agg3 + ((size_t)N_ENT + d) * D) + lane;
    float4* o2 = reinterpret_cast<float4*>(g_agg3 + ((size_t)2 * N_ENT + d) * D) + lane;
    *o0 = a0; *o1 = a1; *o2 = a2;
}

// ================= W fp16 prep + stats zeroing =================
__global__ void k_wsplit(const float* __restrict__ W) {
    int k = blockIdx.x;
    if (k == 0 && threadIdx.x < 128) {
        g_sums[threadIdx.x] = 0.f;
        g_sumsq[threadIdx.x] = 0.f;
    }
    for (int idx = threadIdx.x; idx < D * D; idx += blockDim.x)
        g_Wh[k * D * D + idx] = __float2half(W[k * D * D + idx]);
}

// ================= r0 / rel =================
__global__ void k_r0(const float* __restrict__ coeff,
                     const float* __restrict__ bases,
                     const float* __restrict__ selfr) {
    int b = blockIdx.x, c = threadIdx.x;
    if (b == 200) { g_r0[400 * D + c] = selfr[c]; return; }
    __shared__ float co[N_BASES];
    if (c < N_BASES) co[c] = coeff[b * N_BASES + c];
    __syncthreads();
    float acc = 0.f;
#pragma unroll
    for (int i = 0; i < N_BASES; ++i) acc += co[i] * bases[i * D + c];
    g_r0[b * D + c] = acc;
    g_r0[(200 + b) * D + c] = -acc;
}
__global__ void k_rel(const float* __restrict__ rin,
                      const float* __restrict__ relw,
                      float* __restrict__ rout) {
    int t = blockIdx.x, c = threadIdx.x;
    __shared__ float rr[D];
    rr[c] = rin[t * D + c];
    __syncthreads();
    float acc = 0.f;
#pragma unroll 16
    for (int d = 0; d < D; ++d) acc += rr[d] * relw[d * D + c];
    rout[t * D + c] = acc;
}

// ============ GEMM: out = sum_k agg3[k] @ W[k], fp16 2-term, fused BN stats ===
#define AP 136
#define A_TILE_B (64 * AP * 2)          // 17408
#define W_TILE_B (128 * AP * 2)         // 34816
#define SMEM_DYN (2 * A_TILE_B + W_TILE_B)   // 69632
#define GEMM_BLKS 1563                  // ceil(100000/64)
__global__ __launch_bounds__(256, 3) void k_gemm(const float* __restrict__ agg3,
                                                 float* __restrict__ outp) {
    extern __shared__ unsigned char sm[];
    __half* sAh = reinterpret_cast<__half*>(sm);
    __half* sAl = reinterpret_cast<__half*>(sm + A_TILE_B);
    __half* sWh = reinterpret_cast<__half*>(sm + 2 * A_TILE_B);
    __shared__ float s_sum[D], s_sq[D];

    const int tid = threadIdx.x, wid = tid >> 5, lane = tid & 31;
    const int row0 = blockIdx.x * 64;
    const int wm = wid >> 1, wn = wid & 1;      // 4x2 warp grid
    const int mbase = wm * 16, nbase = wn * 64;

    if (tid < D) { s_sum[tid] = 0.f; s_sq[tid] = 0.f; }

    const uint32_t uAh = smem_u32(sAh), uAl = smem_u32(sAl), uWh = smem_u32(sWh);

    float acc[8][4];
#pragma unroll
    for (int i = 0; i < 8; ++i)
#pragma unroll
        for (int j = 0; j < 4; ++j) acc[i][j] = 0.f;

    for (int k = 0; k < 3; ++k) {
        __syncthreads();
        // W tile (16384 fp16 = 2048 uint4), repitch to AP
        const uint4* gwh = reinterpret_cast<const uint4*>(g_Wh + k * D * D);
#pragma unroll
        for (int i = 0; i < 8; ++i) {
            int idx = tid + i * 256;
            int r = idx >> 4, c8 = (idx & 15) * 8;
            *reinterpret_cast<uint4*>(sWh + r * AP + c8) = gwh[idx];
        }
        // A tile: 64 x 128 fp32, split into fp16 hi/lo
#pragma unroll
        for (int i = 0; i < 8; ++i) {
            int e4 = tid + i * 256;
            int r = e4 >> 5, c = (e4 & 31) * 4;
            float4 v = make_float4(0.f, 0.f, 0.f, 0.f);
            int grow = row0 + r;
            if (grow < N_ENT)
                v = *reinterpret_cast<const float4*>(agg3 + ((size_t)k * N_ENT + grow) * D + c);
            float hx = __half2float(__float2half(v.x));
            float hy = __half2float(__float2half(v.y));
            float hz = __half2float(__float2half(v.z));
            float hw = __half2float(__float2half(v.w));
            *reinterpret_cast<uint2*>(sAh + r * AP + c) = make_uint2(pkh(hx, hy), pkh(hz, hw));
            *reinterpret_cast<uint2*>(sAl + r * AP + c) =
                make_uint2(pkh(v.x - hx, v.y - hy), pkh(v.z - hz, v.w - hw));
        }
        __syncthreads();

#pragma unroll
        for (int ks = 0; ks < 8; ++ks) {
            const int k0 = ks * 16;
            uint32_t ah[4], al[4];
            {
                int row = mbase + (lane & 15);
                int col = k0 + (lane >> 4) * 8;
                uint32_t off = (uint32_t)(row * AP + col) * 2;
                ldsm_x4(ah, uAh + off);
                ldsm_x4(al, uAl + off);
            }
            uint32_t bh[8][2];
#pragma unroll
            for (int p = 0; p < 4; ++p) {
                int row = k0 + ((lane >> 3) & 1) * 8 + (lane & 7);
                int col = nbase + p * 16 + (lane >> 4) * 8;
                uint32_t off = (uint32_t)(row * AP + col) * 2;
                uint32_t t4[4];
                ldsm_x4_t(t4, uWh + off);
                bh[2 * p][0] = t4[0]; bh[2 * p][1] = t4[1];
                bh[2 * p + 1][0] = t4[2]; bh[2 * p + 1][1] = t4[3];
            }
#pragma unroll
            for (int nt = 0; nt < 8; ++nt) {
                mma16816(acc[nt], ah, bh[nt]);
                mma16816(acc[nt], al, bh[nt]);
            }
        }
    }

    // epilogue: store + fused BN stats
    const int g = lane >> 2, t2 = (lane & 3) * 2;
    int r0 = row0 + mbase + g;
    int r1 = r0 + 8;
    bool ok0 = r0 < N_ENT, ok1 = r1 < N_ENT;
#pragma unroll
    for (int nt = 0; nt < 8; ++nt) {
        int col = nbase + nt * 8 + t2;
        if (ok0)
            *reinterpret_cast<float2*>(outp + (size_t)r0 * D + col) =
                make_float2(acc[nt][0], acc[nt][1]);
        if (ok1)
            *reinterpret_cast<float2*>(outp + (size_t)r1 * D + col) =
                make_float2(acc[nt][2], acc[nt][3]);
        // per-thread partial sums for BN stats
        float a0 = ok0 ? acc[nt][0] : 0.f, a1 = ok0 ? acc[nt][1] : 0.f;
        float a2 = ok1 ? acc[nt][2] : 0.f, a3 = ok1 ? acc[nt][3] : 0.f;
        float se = a0 + a2, so = a1 + a3;
        float qe = a0 * a0 + a2 * a2, qo = a1 * a1 + a3 * a3;
#pragma unroll
        for (int off = 16; off >= 4; off >>= 1) {
            se += __shfl_down_sync(0xffffffffu, se, off);
            so += __shfl_down_sync(0xffffffffu, so, off);
            qe += __shfl_down_sync(0xffffffffu, qe, off);
            qo += __shfl_down_sync(0xffffffffu, qo, off);
        }
        if (lane < 4) {
            atomicAdd(&s_sum[col], se);
            atomicAdd(&s_sum[col + 1], so);
            atomicAdd(&s_sq[col], qe);
            atomicAdd(&s_sq[col + 1], qo);
        }
    }
    __syncthreads();
    if (tid < D) {
        atomicAdd(&g_sums[tid], s_sum[tid]);
        atomicAdd(&g_sumsq[tid], s_sq[tid]);
    }
}

// ================= bn finalize / bn+tanh =================
__global__ void k_finalize(const float* __restrict__ gamma,
                           const float* __restrict__ beta) {
    int c = threadIdx.x;
    float inv_n = 1.0f / (float)N_ENT;
    float mean = g_sums[c] * inv_n;
    float var = fmaxf(g_sumsq[c] * inv_n - mean * mean, 0.f);
    float rs = rsqrtf(var + BN_EPS);
    float sc = rs * gamma[c];
    g_scale[c] = sc;
    g_shift[c] = beta[c] - mean * sc;
}
__global__ void k_bntanh(float* __restrict__ xio) {
    int i = blockIdx.x * blockDim.x + threadIdx.x;
    if (i >= N_ENT * D / 4) return;
    int c4 = (i & 31) * 4;
    float4 v = reinterpret_cast<float4*>(xio)[i];
    v.x = tanhf(v.x * g_scale[c4 + 0] + g_shift[c4 + 0]);
    v.y = tanhf(v.y * g_scale[c4 + 1] + g_shift[c4 + 1]);
    v.z = tanhf(v.z * g_scale[c4 + 2] + g_shift[c4 + 2]);
    v.w = tanhf(v.w * g_scale[c4 + 3] + g_shift[c4 + 3]);
    reinterpret_cast<float4*>(xio)[i] = v;
}

// ================= scoring =================
__global__ void k_score(const int* __restrict__ trip, float* __restrict__ out) {
    int t = blockIdx.x * 8 + (threadIdx.x >> 5);
    if (t >= N_TRIPLES_C) return;
    int lane = threadIdx.x & 31;
    int h = trip[t * 3], rl = trip[t * 3 + 1], tl = trip[t * 3 + 2];
    float4 hv = *(reinterpret_cast<const float4*>(g_X2 + (size_t)h * D) + lane);
    float4 rv = *(reinterpret_cast<const float4*>(g_r2 + (size_t)rl * D) + lane);
    float4 tv = *(reinterpret_cast<const float4*>(g_X2 + (size_t)tl * D) + lane);
    float p = fabsf(hv.x + rv.x - tv.x) + fabsf(hv.y + rv.y - tv.y) +
              fabsf(hv.z + rv.z - tv.z) + fabsf(hv.w + rv.w - tv.w);
#pragma unroll
    for (int o = 16; o; o >>= 1) p += __shfl_xor_sync(0xffffffffu, p, o);
    if (lane == 0) out[t] = p;
}

// ================= host side =================
static float* sym_addr_f(const void* sym) {
    void* p = nullptr;
    cudaGetSymbolAddress(&p, sym);
    return reinterpret_cast<float*>(p);
}
static int* sym_addr_i(const void* sym) {
    void* p = nullptr;
    cudaGetSymbolAddress(&p, sym);
    return reinterpret_cast<int*>(p);
}

extern "C" void kernel_launch(void* const* d_in, const int* in_sizes, int n_in,
                              void* d_out, int out_size) {
    (void)in_sizes; (void)n_in; (void)out_size;
    const float* entity = (const float*)d_in[0];
    const float* bases  = (const float*)d_in[1];
    const float* coeff  = (const float*)d_in[2];
    const float* selfr  = (const float*)d_in[3];
    const float* W1     = (const float*)d_in[4];
    const float* relw1  = (const float*)d_in[5];
    const float* g1     = (const float*)d_in[6];
    const float* b1     = (const float*)d_in[7];
    const float* W2     = (const float*)d_in[8];
    const float* relw2  = (const float*)d_in[9];
    const float* g2     = (const float*)d_in[10];
    const float* b2     = (const float*)d_in[11];
    const int* edge_index = (const int*)d_in[13];
    const int* edge_type  = (const int*)d_in[14];
    const int* yv         = (const int*)d_in[15];
    const int* triples    = (const int*)d_in[16];
    float* out = (float*)d_out;

    float* p_r0 = sym_addr_f(g_r0);
    float* p_r1 = sym_addr_f(g_r1);
    float* p_r2 = sym_addr_f(g_r2);
    float* p_agg = sym_addr_f(g_agg3);
    float* p_X1 = sym_addr_f(g_X1);
    float* p_X2 = sym_addr_f(g_X2);
    int* p_deg = sym_addr_i(g_deg);

    cudaFuncSetAttribute(k_gemm, cudaFuncAttributeMaxDynamicSharedMemorySize, SMEM_DYN);

    // ---- CSR build (once; serves both layers) ----
    k_zero_i<<<(N_ENT + 255) / 256, 256>>>(p_deg, N_ENT);
    k_hist<<<(N_EDGES_C + 255) / 256, 256>>>(edge_index);
    k_scan1<<<SCAN_BLKS, 256>>>();
    k_scan2<<<1, 128>>>();
    k_scan3<<<(N_ENT + 255) / 256, 256>>>();
    k_perm<<<(N_EDGES_C + 255) / 256, 256>>>(edge_index, edge_type, yv);

    k_r0<<<201, 128>>>(coeff, bases, selfr);

    // ---- layer 1 ----
    k_wsplit<<<3, 256>>>(W1);          // also zeroes BN stats
    k_aggr<<<N_ENT / 8, 256>>>(entity, p_r0);
    k_gemm<<<GEMM_BLKS, 256, SMEM_DYN>>>(p_agg, p_X1);   // stats fused
    k_finalize<<<1, 128>>>(g1, b1);
    k_bntanh<<<N_ENT * D / 4 / 256, 256>>>(p_X1);
    k_rel<<<N_RELS, 128>>>(p_r0, relw1, p_r1);

    // ---- layer 2 ----
    k_wsplit<<<3, 256>>>(W2);          // re-zeroes BN stats (after finalize1)
    k_aggr<<<N_ENT / 8, 256>>>(p_X1, p_r1);
    k_gemm<<<GEMM_BLKS, 256, SMEM_DYN>>>(p_agg, p_X2);
    k_finalize<<<1, 128>>>(g2, b2);
    k_bntanh<<<N_ENT * D / 4 / 256, 256>>>(p_X2);
    k_rel<<<N_RELS, 128>>>(p_r1, relw2, p_r2);

    // ---- scoring ----
    k_score<<<N_TRIPLES_C / 8, 256>>>(triples, out);
}

// round 7
// speedup vs baseline: 2.6934x; 1.1867x over previous
#include <cuda_runtime.h>
#include <cuda_fp16.h>
#include <cstdint>
#include <cstddef>

// ---------------- problem constants ----------------
#define N_ENT      100000
#define N_RELS     401
#define N_BASES    50
#define D          128
#define N_EDGES_C  800000
#define N_TRIPLES_C 4096
#define BN_EPS     1e-5f
#define SCAN_BLKS  98             // 98 * 1024 >= 100000

// ---------------- scratch ----------------
__device__ float g_r0[N_RELS * D];
__device__ float g_r1[N_RELS * D];
__device__ float g_r2[N_RELS * D];
__device__ __half g_agg3h[(size_t)3 * N_ENT * D];      // per-class aggregates, fp16 (76.8 MB)
__device__ float g_X1[(size_t)N_ENT * D];
__device__ float g_X2[(size_t)N_ENT * D];
__device__ float g_sums[D];
__device__ float g_sumsq[D];
__device__ float g_scale[D];
__device__ float g_shift[D];
__device__ __half g_Wh[3 * D * D];                     // fp16 W[k], [k][kk][n]
// CSR
__device__ int g_deg[N_ENT];
__device__ int g_rs[N_ENT];
__device__ int g_cur[N_ENT];
__device__ int g_bsum[SCAN_BLKS];
__device__ int g_esrc[N_EDGES_C];
__device__ int g_emeta[N_EDGES_C];     // et | (y<<16)

// ---------------- helpers ----------------
__device__ __forceinline__ uint32_t smem_u32(const void* p) {
    uint32_t a;
    asm("{ .reg .u64 t; cvta.to.shared.u64 t, %1; cvt.u32.u64 %0, t; }" : "=r"(a) : "l"(p));
    return a;
}
__device__ __forceinline__ uint32_t pkh(float a, float b) {
    __half2 t = __floats2half2_rn(a, b);
    return *reinterpret_cast<uint32_t*>(&t);
}
__device__ __forceinline__ void ldsm_x4(uint32_t* r, uint32_t addr) {
    asm volatile("ldmatrix.sync.aligned.m8n8.x4.shared.b16 {%0,%1,%2,%3}, [%4];"
                 : "=r"(r[0]), "=r"(r[1]), "=r"(r[2]), "=r"(r[3]) : "r"(addr));
}
__device__ __forceinline__ void ldsm_x4_t(uint32_t* r, uint32_t addr) {
    asm volatile("ldmatrix.sync.aligned.m8n8.x4.trans.shared.b16 {%0,%1,%2,%3}, [%4];"
                 : "=r"(r[0]), "=r"(r[1]), "=r"(r[2]), "=r"(r[3]) : "r"(addr));
}
__device__ __forceinline__ void mma16816(float* c, const uint32_t* a, const uint32_t* b) {
    asm volatile(
        "mma.sync.aligned.m16n8k16.row.col.f32.f16.f16.f32 "
        "{%0,%1,%2,%3}, {%4,%5,%6,%7}, {%8,%9}, {%0,%1,%2,%3};"
        : "+f"(c[0]), "+f"(c[1]), "+f"(c[2]), "+f"(c[3])
        : "r"(a[0]), "r"(a[1]), "r"(a[2]), "r"(a[3]), "r"(b[0]), "r"(b[1]));
}

// ================= r0 + deg-zero combined =================
__global__ void k_r0z(const float* __restrict__ coeff,
                      const float* __restrict__ bases,
                      const float* __restrict__ selfr) {
    int b = blockIdx.x;
    if (b >= 201) {
        int i = (b - 201) * 256 + threadIdx.x;
        if (i < N_ENT) g_deg[i] = 0;
        return;
    }
    int c = threadIdx.x;
    if (c >= 128) return;
    if (b == 200) { g_r0[400 * D + c] = selfr[c]; return; }
    __shared__ float co[N_BASES];
    if (c < N_BASES) co[c] = coeff[b * N_BASES + c];
    __syncthreads();
    float acc = 0.f;
#pragma unroll
    for (int i = 0; i < N_BASES; ++i) acc += co[i] * bases[i * D + c];
    g_r0[b * D + c] = acc;
    g_r0[(200 + b) * D + c] = -acc;
}

// ================= CSR build =================
__global__ void k_hist(const int* __restrict__ ei) {
    int e = blockIdx.x * blockDim.x + threadIdx.x;
    if (e < N_EDGES_C) atomicAdd(&g_deg[ei[N_EDGES_C + e]], 1);
}
__global__ void k_scan1() {
    __shared__ int ts[256];
    int b = blockIdx.x, t = threadIdx.x;
    int base = b * 1024 + t * 4;
    int v[4];
#pragma unroll
    for (int j = 0; j < 4; ++j)
        v[j] = (base + j < N_ENT) ? g_deg[base + j] : 0;
    int s = v[0] + v[1] + v[2] + v[3];
    ts[t] = s;
    __syncthreads();
    for (int off = 1; off < 256; off <<= 1) {
        int x = (t >= off) ? ts[t - off] : 0;
        __syncthreads();
        ts[t] += x;
        __syncthreads();
    }
    int excl = ts[t] - s;
    if (t == 255) g_bsum[b] = ts[255];
#pragma unroll
    for (int j = 0; j < 4; ++j) {
        if (base + j < N_ENT) g_rs[base + j] = excl;
        excl += v[j];
    }
}
// scan of block sums folded in: each block recomputes the 98-elem prefix locally
__global__ void k_scan3() {
    __shared__ int s_pref[SCAN_BLKS];
    if (threadIdx.x == 0) {
        int acc = 0;
#pragma unroll 2
        for (int j = 0; j < SCAN_BLKS; ++j) { s_pref[j] = acc; acc += g_bsum[j]; }
    }
    __syncthreads();
    int i = blockIdx.x * blockDim.x + threadIdx.x;
    if (i < N_ENT) {
        int v = g_rs[i] + s_pref[i >> 10];
        g_rs[i] = v;
        g_cur[i] = v;
    }
}
__global__ void k_perm(const int* __restrict__ ei,
                       const int* __restrict__ et,
                       const int* __restrict__ yv) {
    int e = blockIdx.x * blockDim.x + threadIdx.x;
    if (e >= N_EDGES_C) return;
    int dst = ei[N_EDGES_C + e];
    int pos = atomicAdd(&g_cur[dst], 1);
    g_esrc[pos] = ei[e];
    g_emeta[pos] = et[e] | (yv[e] << 16);
}

// ================= per-dst aggregation -> fp16 agg3 =================
__global__ __launch_bounds__(256) void k_aggr(const float* __restrict__ x,
                                              const float* __restrict__ rtab) {
    int d = blockIdx.x * 8 + (threadIdx.x >> 5);
    if (d >= N_ENT) return;
    int lane = threadIdx.x & 31;
    int start = g_rs[d];
    int end = start + g_deg[d];
    float4 a0 = make_float4(0.f, 0.f, 0.f, 0.f), a1 = a0, a2 = a0;
    for (int i = start; i < end; ++i) {
        int src = __ldg(g_esrc + i);
        int m = __ldg(g_emeta + i);
        int tt = m & 0xFFFF, y = m >> 16;
        float4 xv = __ldg(reinterpret_cast<const float4*>(x + (size_t)src * D) + lane);
        float4 rv = __ldg(reinterpret_cast<const float4*>(rtab + (size_t)tt * D) + lane);
        float4 v = make_float4(xv.x - rv.x, xv.y - rv.y, xv.z - rv.z, xv.w - rv.w);
        if (y == 0)      { a0.x += v.x; a0.y += v.y; a0.z += v.z; a0.w += v.w; }
        else if (y == 1) { a1.x += v.x; a1.y += v.y; a1.z += v.z; a1.w += v.w; }
        else             { a2.x += v.x; a2.y += v.y; a2.z += v.z; a2.w += v.w; }
    }
    uint2* o0 = reinterpret_cast<uint2*>(g_agg3h + (size_t)d * D) + lane;
    uint2* o1 = reinterpret_cast<uint2*>(g_agg3h + ((size_t)N_ENT + d) * D) + lane;
    uint2* o2 = reinterpret_cast<uint2*>(g_agg3h + ((size_t)2 * N_ENT + d) * D) + lane;
    *o0 = make_uint2(pkh(a0.x, a0.y), pkh(a0.z, a0.w));
    *o1 = make_uint2(pkh(a1.x, a1.y), pkh(a1.z, a1.w));
    *o2 = make_uint2(pkh(a2.x, a2.y), pkh(a2.z, a2.w));
}

// ================= W fp16 prep + stats zeroing =================
__global__ void k_wsplit(const float* __restrict__ W) {
    int k = blockIdx.x;
    if (k == 0 && threadIdx.x < 128) {
        g_sums[threadIdx.x] = 0.f;
        g_sumsq[threadIdx.x] = 0.f;
    }
    for (int idx = threadIdx.x; idx < D * D; idx += blockDim.x)
        g_Wh[k * D * D + idx] = __float2half(W[k * D * D + idx]);
}

// ================= rel =================
__global__ void k_rel(const float* __restrict__ rin,
                      const float* __restrict__ relw,
                      float* __restrict__ rout) {
    int t = blockIdx.x, c = threadIdx.x;
    __shared__ float rr[D];
    rr[c] = rin[t * D + c];
    __syncthreads();
    float acc = 0.f;
#pragma unroll 16
    for (int d = 0; d < D; ++d) acc += rr[d] * relw[d * D + c];
    rout[t * D + c] = acc;
}

// ============ GEMM: out = sum_k agg3h[k] @ W[k], fp16 1-term, fused BN stats ==
#define AP 136
#define A_TILE_B (64 * AP * 2)          // 17408
#define W_TILE_B (128 * AP * 2)         // 34816
#define SMEM_DYN (A_TILE_B + W_TILE_B)  // 52224
#define GEMM_BLKS 1563                  // ceil(100000/64)
__global__ __launch_bounds__(256, 4) void k_gemm(float* __restrict__ outp) {
    extern __shared__ unsigned char sm[];
    __half* sA = reinterpret_cast<__half*>(sm);
    __half* sW = reinterpret_cast<__half*>(sm + A_TILE_B);
    __shared__ float s_sum[D], s_sq[D];

    const int tid = threadIdx.x, wid = tid >> 5, lane = tid & 31;
    const int row0 = blockIdx.x * 64;
    const int wm = wid >> 1, wn = wid & 1;      // 4x2 warp grid
    const int mbase = wm * 16, nbase = wn * 64;

    if (tid < D) { s_sum[tid] = 0.f; s_sq[tid] = 0.f; }

    const uint32_t uA = smem_u32(sA), uW = smem_u32(sW);

    float acc[8][4];
#pragma unroll
    for (int i = 0; i < 8; ++i)
#pragma unroll
        for (int j = 0; j < 4; ++j) acc[i][j] = 0.f;

    for (int k = 0; k < 3; ++k) {
        __syncthreads();
        // W tile (16384 fp16 = 2048 uint4), repitch to AP
        const uint4* gw = reinterpret_cast<const uint4*>(g_Wh + k * D * D);
#pragma unroll
        for (int i = 0; i < 8; ++i) {
            int idx = tid + i * 256;
            int r = idx >> 4, c8 = (idx & 15) * 8;
            *reinterpret_cast<uint4*>(sW + r * AP + c8) = gw[idx];
        }
        // A tile: 64 x 128 fp16 = 1024 uint4
        const __half* ga = g_agg3h + (size_t)k * N_ENT * D;
#pragma unroll
        for (int i = 0; i < 4; ++i) {
            int idx = tid + i * 256;
            int r = idx >> 4, c8 = (idx & 15) * 8;
            int grow = row0 + r;
            uint4 v = make_uint4(0u, 0u, 0u, 0u);
            if (grow < N_ENT)
                v = *reinterpret_cast<const uint4*>(ga + (size_t)grow * D + c8);
            *reinterpret_cast<uint4*>(sA + r * AP + c8) = v;
        }
        __syncthreads();

#pragma unroll
        for (int ks = 0; ks < 8; ++ks) {
            const int k0 = ks * 16;
            uint32_t ah[4];
            {
                int row = mbase + (lane & 15);
                int col = k0 + (lane >> 4) * 8;
                ldsm_x4(ah, uA + (uint32_t)(row * AP + col) * 2);
            }
            uint32_t bh[8][2];
#pragma unroll
            for (int p = 0; p < 4; ++p) {
                int row = k0 + ((lane >> 3) & 1) * 8 + (lane & 7);
                int col = nbase + p * 16 + (lane >> 4) * 8;
                uint32_t t4[4];
                ldsm_x4_t(t4, uW + (uint32_t)(row * AP + col) * 2);
                bh[2 * p][0] = t4[0]; bh[2 * p][1] = t4[1];
                bh[2 * p + 1][0] = t4[2]; bh[2 * p + 1][1] = t4[3];
            }
#pragma unroll
            for (int nt = 0; nt < 8; ++nt)
                mma16816(acc[nt], ah, bh[nt]);
        }
    }

    // epilogue: store + fused BN stats
    const int g = lane >> 2, t2 = (lane & 3) * 2;
    int r0 = row0 + mbase + g;
    int r1 = r0 + 8;
    bool ok0 = r0 < N_ENT, ok1 = r1 < N_ENT;
#pragma unroll
    for (int nt = 0; nt < 8; ++nt) {
        int col = nbase + nt * 8 + t2;
        if (ok0)
            *reinterpret_cast<float2*>(outp + (size_t)r0 * D + col) =
                make_float2(acc[nt][0], acc[nt][1]);
        if (ok1)
            *reinterpret_cast<float2*>(outp + (size_t)r1 * D + col) =
                make_float2(acc[nt][2], acc[nt][3]);
        float a0 = ok0 ? acc[nt][0] : 0.f, a1 = ok0 ? acc[nt][1] : 0.f;
        float a2 = ok1 ? acc[nt][2] : 0.f, a3 = ok1 ? acc[nt][3] : 0.f;
        float se = a0 + a2, so = a1 + a3;
        float qe = a0 * a0 + a2 * a2, qo = a1 * a1 + a3 * a3;
#pragma unroll
        for (int off = 16; off >= 4; off >>= 1) {
            se += __shfl_down_sync(0xffffffffu, se, off);
            so += __shfl_down_sync(0xffffffffu, so, off);
            qe += __shfl_down_sync(0xffffffffu, qe, off);
            qo += __shfl_down_sync(0xffffffffu, qo, off);
        }
        if (lane < 4) {
            atomicAdd(&s_sum[col], se);
            atomicAdd(&s_sum[col + 1], so);
            atomicAdd(&s_sq[col], qe);
            atomicAdd(&s_sq[col + 1], qo);
        }
    }
    __syncthreads();
    if (tid < D) {
        atomicAdd(&g_sums[tid], s_sum[tid]);
        atomicAdd(&g_sumsq[tid], s_sq[tid]);
    }
}

// ================= bn finalize / bn+tanh =================
__global__ void k_finalize(const float* __restrict__ gamma,
                           const float* __restrict__ beta) {
    int c = threadIdx.x;
    float inv_n = 1.0f / (float)N_ENT;
    float mean = g_sums[c] * inv_n;
    float var = fmaxf(g_sumsq[c] * inv_n - mean * mean, 0.f);
    float rs = rsqrtf(var + BN_EPS);
    float sc = rs * gamma[c];
    g_scale[c] = sc;
    g_shift[c] = beta[c] - mean * sc;
}
__global__ void k_bntanh(float* __restrict__ xio) {
    int i = blockIdx.x * blockDim.x + threadIdx.x;
    if (i >= N_ENT * D / 4) return;
    int c4 = (i & 31) * 4;
    float4 v = reinterpret_cast<float4*>(xio)[i];
    v.x = tanhf(v.x * g_scale[c4 + 0] + g_shift[c4 + 0]);
    v.y = tanhf(v.y * g_scale[c4 + 1] + g_shift[c4 + 1]);
    v.z = tanhf(v.z * g_scale[c4 + 2] + g_shift[c4 + 2]);
    v.w = tanhf(v.w * g_scale[c4 + 3] + g_shift[c4 + 3]);
    reinterpret_cast<float4*>(xio)[i] = v;
}

// ================= scoring (BN+tanh of layer 2 fused here) =================
__global__ void k_score(const int* __restrict__ trip, float* __restrict__ out) {
    int t = blockIdx.x * 8 + (threadIdx.x >> 5);
    if (t >= N_TRIPLES_C) return;
    int lane = threadIdx.x & 31;
    int h = trip[t * 3], rl = trip[t * 3 + 1], tl = trip[t * 3 + 2];
    float4 sc = *(reinterpret_cast<const float4*>(g_scale) + lane);
    float4 sh = *(reinterpret_cast<const float4*>(g_shift) + lane);
    float4 hv = *(reinterpret_cast<const float4*>(g_X2 + (size_t)h * D) + lane);
    float4 rv = *(reinterpret_cast<const float4*>(g_r2 + (size_t)rl * D) + lane);
    float4 tv = *(reinterpret_cast<const float4*>(g_X2 + (size_t)tl * D) + lane);
    float hx = tanhf(hv.x * sc.x + sh.x), tx = tanhf(tv.x * sc.x + sh.x);
    float hy = tanhf(hv.y * sc.y + sh.y), ty = tanhf(tv.y * sc.y + sh.y);
    float hz = tanhf(hv.z * sc.z + sh.z), tz = tanhf(tv.z * sc.z + sh.z);
    float hw = tanhf(hv.w * sc.w + sh.w), tw = tanhf(tv.w * sc.w + sh.w);
    float p = fabsf(hx + rv.x - tx) + fabsf(hy + rv.y - ty) +
              fabsf(hz + rv.z - tz) + fabsf(hw + rv.w - tw);
#pragma unroll
    for (int o = 16; o; o >>= 1) p += __shfl_xor_sync(0xffffffffu, p, o);
    if (lane == 0) out[t] = p;
}

// ================= host side =================
static float* sym_addr_f(const void* sym) {
    void* p = nullptr;
    cudaGetSymbolAddress(&p, sym);
    return reinterpret_cast<float*>(p);
}

extern "C" void kernel_launch(void* const* d_in, const int* in_sizes, int n_in,
                              void* d_out, int out_size) {
    (void)in_sizes; (void)n_in; (void)out_size;
    const float* entity = (const float*)d_in[0];
    const float* bases  = (const float*)d_in[1];
    const float* coeff  = (const float*)d_in[2];
    const float* selfr  = (const float*)d_in[3];
    const float* W1     = (const float*)d_in[4];
    const float* relw1  = (const float*)d_in[5];
    const float* g1     = (const float*)d_in[6];
    const float* b1     = (const float*)d_in[7];
    const float* W2     = (const float*)d_in[8];
    const float* relw2  = (const float*)d_in[9];
    const float* g2     = (const float*)d_in[10];
    const float* b2     = (const float*)d_in[11];
    const int* edge_index = (const int*)d_in[13];
    const int* edge_type  = (const int*)d_in[14];
    const int* yv         = (const int*)d_in[15];
    const int* triples    = (const int*)d_in[16];
    float* out = (float*)d_out;

    float* p_r0 = sym_addr_f(g_r0);
    float* p_r1 = sym_addr_f(g_r1);
    float* p_r2 = sym_addr_f(g_r2);
    float* p_X1 = sym_addr_f(g_X1);
    float* p_X2 = sym_addr_f(g_X2);

    cudaFuncSetAttribute(k_gemm, cudaFuncAttributeMaxDynamicSharedMemorySize, SMEM_DYN);

    // ---- r0 + CSR build (once; serves both layers) ----
    k_r0z<<<201 + (N_ENT + 255) / 256, 256>>>(coeff, bases, selfr);
    k_hist<<<(N_EDGES_C + 255) / 256, 256>>>(edge_index);
    k_scan1<<<SCAN_BLKS, 256>>>();
    k_scan3<<<(N_ENT + 255) / 256, 256>>>();
    k_perm<<<(N_EDGES_C + 255) / 256, 256>>>(edge_index, edge_type, yv);

    // ---- layer 1 ----
    k_wsplit<<<3, 256>>>(W1);          // also zeroes BN stats
    k_aggr<<<N_ENT / 8, 256>>>(entity, p_r0);
    k_gemm<<<GEMM_BLKS, 256, SMEM_DYN>>>(p_X1);          // stats fused
    k_finalize<<<1, 128>>>(g1, b1);
    k_bntanh<<<N_ENT * D / 4 / 256, 256>>>(p_X1);
    k_rel<<<N_RELS, 128>>>(p_r0, relw1, p_r1);

    // ---- layer 2 ----
    k_wsplit<<<3, 256>>>(W2);          // re-zeroes BN stats (after finalize1)
    k_aggr<<<N_ENT / 8, 256>>>(p_X1, p_r1);
    k_gemm<<<GEMM_BLKS, 256, SMEM_DYN>>>(p_X2);
    k_finalize<<<1, 128>>>(g2, b2);
    k_rel<<<N_RELS, 128>>>(p_r1, relw2, p_r2);

    // ---- scoring (applies layer-2 BN+tanh on the fly) ----
    k_score<<<N_TRIPLES_C / 8, 256>>>(triples, out);
}

// round 9
// speedup vs baseline: 3.0970x; 1.1498x over previous
#include <cuda_runtime.h>
#include <cuda_fp16.h>
#include <cstdint>
#include <cstddef>

// ---------------- problem constants ----------------
#define N_ENT      100000
#define N_RELS     401
#define N_BASES    50
#define D          128
#define N_EDGES_C  800000
#define N_TRIPLES_C 4096
#define BN_EPS     1e-5f
#define SCAN_BLKS  98             // 98 * 1024 >= 100000

// ---------------- scratch ----------------
__device__ float g_r0[N_RELS * D];
__device__ float g_r1[N_RELS * D];
__device__ float g_r2[N_RELS * D];
__device__ __half g_rh[N_RELS * D];                    // fp16 gather copy of current r
__device__ __half g_xh[(size_t)N_ENT * D];             // fp16 gather copy of current x (25.6 MB)
__device__ __half g_agg3h[(size_t)3 * N_ENT * D];      // per-class aggregates, fp16 (76.8 MB)
__device__ float g_X1[(size_t)N_ENT * D];
__device__ float g_X2[(size_t)N_ENT * D];
__device__ float g_sums[2 * D];
__device__ float g_sumsq[2 * D];
__device__ float g_scale[D];
__device__ float g_shift[D];
__device__ __half g_Wh[6 * D * D];                     // fp16 W1[0..2], W2[0..2]
// CSR
__device__ int g_deg[N_ENT];
__device__ int g_rs[N_ENT];
__device__ int g_cur[N_ENT];
__device__ int g_bsum[SCAN_BLKS];
__device__ int2 g_edge[N_EDGES_C];     // (src, et | y<<16)

// ---------------- helpers ----------------
__device__ __forceinline__ uint32_t smem_u32(const void* p) {
    uint32_t a;
    asm("{ .reg .u64 t; cvta.to.shared.u64 t, %1; cvt.u32.u64 %0, t; }" : "=r"(a) : "l"(p));
    return a;
}
__device__ __forceinline__ uint32_t pkh(float a, float b) {
    __half2 t = __floats2half2_rn(a, b);
    return *reinterpret_cast<uint32_t*>(&t);
}
__device__ __forceinline__ void ldsm_x4(uint32_t* r, uint32_t addr) {
    asm volatile("ldmatrix.sync.aligned.m8n8.x4.shared.b16 {%0,%1,%2,%3}, [%4];"
                 : "=r"(r[0]), "=r"(r[1]), "=r"(r[2]), "=r"(r[3]) : "r"(addr));
}
__device__ __forceinline__ void ldsm_x4_t(uint32_t* r, uint32_t addr) {
    asm volatile("ldmatrix.sync.aligned.m8n8.x4.trans.shared.b16 {%0,%1,%2,%3}, [%4];"
                 : "=r"(r[0]), "=r"(r[1]), "=r"(r[2]), "=r"(r[3]) : "r"(addr));
}
__device__ __forceinline__ void mma16816(float* c, const uint32_t* a, const uint32_t* b) {
    asm volatile(
        "mma.sync.aligned.m16n8k16.row.col.f32.f16.f16.f32 "
        "{%0,%1,%2,%3}, {%4,%5,%6,%7}, {%8,%9}, {%0,%1,%2,%3};"
        : "+f"(c[0]), "+f"(c[1]), "+f"(c[2]), "+f"(c[3])
        : "r"(a[0]), "r"(a[1]), "r"(a[2]), "r"(a[3]), "r"(b[0]), "r"(b[1]));
}

// ================= r0 (fp32 + fp16) + deg-zero combined =================
__global__ void k_r0z(const float* __restrict__ coeff,
                      const float* __restrict__ bases,
                      const float* __restrict__ selfr) {
    int b = blockIdx.x;
    if (b >= 201) {
        int i = (b - 201) * 256 + threadIdx.x;
        if (i < N_ENT) g_deg[i] = 0;
        return;
    }
    int c = threadIdx.x;
    if (c >= 128) return;
    if (b == 200) {
        float v = selfr[c];
        g_r0[400 * D + c] = v;
        g_rh[400 * D + c] = __float2half(v);
        return;
    }
    __shared__ float co[N_BASES];
    if (c < N_BASES) co[c] = coeff[b * N_BASES + c];
    __syncthreads();
    float acc = 0.f;
#pragma unroll
    for (int i = 0; i < N_BASES; ++i) acc += co[i] * bases[i * D + c];
    g_r0[b * D + c] = acc;
    g_r0[(200 + b) * D + c] = -acc;
    g_rh[b * D + c] = __float2half(acc);
    g_rh[(200 + b) * D + c] = __float2half(-acc);
}

// ================= entity -> fp16 table =================
__global__ void k_xconv(const float* __restrict__ x) {
    int i = blockIdx.x * 256 + threadIdx.x;
    if (i < N_ENT * D / 4) {
        float4 v = reinterpret_cast<const float4*>(x)[i];
        reinterpret_cast<uint2*>(g_xh)[i] = make_uint2(pkh(v.x, v.y), pkh(v.z, v.w));
    }
}

// ================= CSR build =================
__global__ void k_hist(const int* __restrict__ ei) {
    int e = blockIdx.x * blockDim.x + threadIdx.x;
    if (e < N_EDGES_C) atomicAdd(&g_deg[ei[N_EDGES_C + e]], 1);
}
__global__ void k_scan1() {
    __shared__ int ts[256];
    int b = blockIdx.x, t = threadIdx.x;
    int base = b * 1024 + t * 4;
    int v[4];
#pragma unroll
    for (int j = 0; j < 4; ++j)
        v[j] = (base + j < N_ENT) ? g_deg[base + j] : 0;
    int s = v[0] + v[1] + v[2] + v[3];
    ts[t] = s;
    __syncthreads();
    for (int off = 1; off < 256; off <<= 1) {
        int x = (t >= off) ? ts[t - off] : 0;
        __syncthreads();
        ts[t] += x;
        __syncthreads();
    }
    int excl = ts[t] - s;
    if (t == 255) g_bsum[b] = ts[255];
#pragma unroll
    for (int j = 0; j < 4; ++j) {
        if (base + j < N_ENT) g_rs[base + j] = excl;
        excl += v[j];
    }
}
__global__ void k_scan3() {
    __shared__ int ts[128];
    __shared__ int s_pref[128];
    int t = threadIdx.x;
    int v0 = 0;
    if (t < 128) {
        v0 = (t < SCAN_BLKS) ? g_bsum[t] : 0;
        ts[t] = v0;
    }
    __syncthreads();
    for (int off = 1; off < 128; off <<= 1) {
        int x = (t >= off && t < 128) ? ts[t - off] : 0;
        __syncthreads();
        if (t < 128) ts[t] += x;
        __syncthreads();
    }
    if (t < 128) s_pref[t] = ts[t] - v0;      // exclusive prefix of block sums
    __syncthreads();
    int i = blockIdx.x * 256 + t;
    if (i < N_ENT) {
        int v = g_rs[i] + s_pref[i >> 10];
        g_rs[i] = v;
        g_cur[i] = v;
    }
}
__global__ void k_perm(const int* __restrict__ ei,
                       const int* __restrict__ et,
                       const int* __restrict__ yv) {
    int e = blockIdx.x * blockDim.x + threadIdx.x;
    if (e >= N_EDGES_C) return;
    int dst = ei[N_EDGES_C + e];
    int pos = atomicAdd(&g_cur[dst], 1);
    g_edge[pos] = make_int2(ei[e], et[e] | (yv[e] << 16));
}

// ================= per-dst aggregation (fp16 gather -> fp16 agg3) ===========
__global__ __launch_bounds__(256) void k_aggr() {
    int d = blockIdx.x * 8 + (threadIdx.x >> 5);
    if (d >= N_ENT) return;
    int lane = threadIdx.x & 31;
    int start = g_rs[d];
    int end = start + g_deg[d];
    float4 a0 = make_float4(0.f, 0.f, 0.f, 0.f), a1 = a0, a2 = a0;
    for (int i = start; i < end; ++i) {
        int2 em = __ldg(&g_edge[i]);
        int src = em.x;
        int tt = em.y & 0xFFFF, y = em.y >> 16;
        uint2 xv = __ldg(reinterpret_cast<const uint2*>(g_xh + (size_t)src * D) + lane);
        uint2 rv = __ldg(reinterpret_cast<const uint2*>(g_rh + (size_t)tt * D) + lane);
        float2 x01 = __half22float2(*reinterpret_cast<__half2*>(&xv.x));
        float2 x23 = __half22float2(*reinterpret_cast<__half2*>(&xv.y));
        float2 r01 = __half22float2(*reinterpret_cast<__half2*>(&rv.x));
        float2 r23 = __half22float2(*reinterpret_cast<__half2*>(&rv.y));
        float4 v = make_float4(x01.x - r01.x, x01.y - r01.y, x23.x - r23.x, x23.y - r23.y);
        if (y == 0)      { a0.x += v.x; a0.y += v.y; a0.z += v.z; a0.w += v.w; }
        else if (y == 1) { a1.x += v.x; a1.y += v.y; a1.z += v.z; a1.w += v.w; }
        else             { a2.x += v.x; a2.y += v.y; a2.z += v.z; a2.w += v.w; }
    }
    uint2* o0 = reinterpret_cast<uint2*>(g_agg3h + (size_t)d * D) + lane;
    uint2* o1 = reinterpret_cast<uint2*>(g_agg3h + ((size_t)N_ENT + d) * D) + lane;
    uint2* o2 = reinterpret_cast<uint2*>(g_agg3h + ((size_t)2 * N_ENT + d) * D) + lane;
    *o0 = make_uint2(pkh(a0.x, a0.y), pkh(a0.z, a0.w));
    *o1 = make_uint2(pkh(a1.x, a1.y), pkh(a1.z, a1.w));
    *o2 = make_uint2(pkh(a2.x, a2.y), pkh(a2.z, a2.w));
}

// ================= W fp16 prep (both layers) + stats zeroing =================
__global__ void k_wsplit2(const float* __restrict__ W1,
                          const float* __restrict__ W2) {
    int k = blockIdx.x;                 // 0..5
    if (k == 0 && threadIdx.x < 256) {
        g_sums[threadIdx.x] = 0.f;
        g_sumsq[threadIdx.x] = 0.f;
    }
    const float* W = (k < 3) ? (W1 + k * D * D) : (W2 + (k - 3) * D * D);
    for (int idx = threadIdx.x; idx < D * D; idx += blockDim.x)
        g_Wh[k * D * D + idx] = __float2half(W[idx]);
}

// ================= rel (+ fused BN finalize as extra block) =================
__global__ void k_rel(const float* __restrict__ rin,
                      const float* __restrict__ relw,
                      float* __restrict__ rout,
                      __half* __restrict__ routh,
                      const float* __restrict__ gamma,
                      const float* __restrict__ beta,
                      const float* __restrict__ sums,
                      const float* __restrict__ sumsq) {
    int t = blockIdx.x, c = threadIdx.x;
    if (t == N_RELS) {                  // finalize block
        float inv_n = 1.0f / (float)N_ENT;
        float mean = sums[c] * inv_n;
        float var = fmaxf(sumsq[c] * inv_n - mean * mean, 0.f);
        float rs = rsqrtf(var + BN_EPS);
        float sc = rs * gamma[c];
        g_scale[c] = sc;
        g_shift[c] = beta[c] - mean * sc;
        return;
    }
    __shared__ float rr[D];
    rr[c] = rin[t * D + c];
    __syncthreads();
    float acc = 0.f;
#pragma unroll 16
    for (int d = 0; d < D; ++d) acc += rr[d] * relw[d * D + c];
    rout[t * D + c] = acc;
    if (routh) routh[t * D + c] = __float2half(acc);
}

// ============ GEMM: out = sum_k agg3h[k] @ W[k], fused BN stats ==============
#define AP 136
#define A_TILE_B (64 * AP * 2)          // 17408
#define W_TILE_B (128 * AP * 2)         // 34816
#define SMEM_DYN (A_TILE_B + W_TILE_B)  // 52224
#define GEMM_BLKS 1563                  // ceil(100000/64)
__global__ __launch_bounds__(256, 4) void k_gemm(float* __restrict__ outp,
                                                 const __half* __restrict__ Wset,
                                                 float* __restrict__ sums,
                                                 float* __restrict__ sumsq) {
    extern __shared__ unsigned char sm[];
    __half* sA = reinterpret_cast<__half*>(sm);
    __half* sW = reinterpret_cast<__half*>(sm + A_TILE_B);
    __shared__ float s_sum[D], s_sq[D];

    const int tid = threadIdx.x, wid = tid >> 5, lane = tid & 31;
    const int row0 = blockIdx.x * 64;
    const int wm = wid >> 1, wn = wid & 1;
    const int mbase = wm * 16, nbase = wn * 64;

    if (tid < D) { s_sum[tid] = 0.f; s_sq[tid] = 0.f; }

    const uint32_t uA = smem_u32(sA), uW = smem_u32(sW);

    float acc[8][4];
#pragma unroll
    for (int i = 0; i < 8; ++i)
#pragma unroll
        for (int j = 0; j < 4; ++j) acc[i][j] = 0.f;

    for (int k = 0; k < 3; ++k) {
        __syncthreads();
        const uint4* gw = reinterpret_cast<const uint4*>(Wset + k * D * D);
#pragma unroll
        for (int i = 0; i < 8; ++i) {
            int idx = tid + i * 256;
            int r = idx >> 4, c8 = (idx & 15) * 8;
            *reinterpret_cast<uint4*>(sW + r * AP + c8) = gw[idx];
        }
        const __half* ga = g_agg3h + (size_t)k * N_ENT * D;
#pragma unroll
        for (int i = 0; i < 4; ++i) {
            int idx = tid + i * 256;
            int r = idx >> 4, c8 = (idx & 15) * 8;
            int grow = row0 + r;
            uint4 v = make_uint4(0u, 0u, 0u, 0u);
            if (grow < N_ENT)
                v = *reinterpret_cast<const uint4*>(ga + (size_t)grow * D + c8);
            *reinterpret_cast<uint4*>(sA + r * AP + c8) = v;
        }
        __syncthreads();

#pragma unroll
        for (int ks = 0; ks < 8; ++ks) {
            const int k0 = ks * 16;
            uint32_t ah[4];
            {
                int row = mbase + (lane & 15);
                int col = k0 + (lane >> 4) * 8;
                ldsm_x4(ah, uA + (uint32_t)(row * AP + col) * 2);
            }
            uint32_t bh[8][2];
#pragma unroll
            for (int p = 0; p < 4; ++p) {
                int row = k0 + ((lane >> 3) & 1) * 8 + (lane & 7);
                int col = nbase + p * 16 + (lane >> 4) * 8;
                uint32_t t4[4];
                ldsm_x4_t(t4, uW + (uint32_t)(row * AP + col) * 2);
                bh[2 * p][0] = t4[0]; bh[2 * p][1] = t4[1];
                bh[2 * p + 1][0] = t4[2]; bh[2 * p + 1][1] = t4[3];
            }
#pragma unroll
            for (int nt = 0; nt < 8; ++nt)
                mma16816(acc[nt], ah, bh[nt]);
        }
    }

    const int g = lane >> 2, t2 = (lane & 3) * 2;
    int r0 = row0 + mbase + g;
    int r1 = r0 + 8;
    bool ok0 = r0 < N_ENT, ok1 = r1 < N_ENT;
#pragma unroll
    for (int nt = 0; nt < 8; ++nt) {
        int col = nbase + nt * 8 + t2;
        if (ok0)
            *reinterpret_cast<float2*>(outp + (size_t)r0 * D + col) =
                make_float2(acc[nt][0], acc[nt][1]);
        if (ok1)
            *reinterpret_cast<float2*>(outp + (size_t)r1 * D + col) =
                make_float2(acc[nt][2], acc[nt][3]);
        float a0 = ok0 ? acc[nt][0] : 0.f, a1 = ok0 ? acc[nt][1] : 0.f;
        float a2 = ok1 ? acc[nt][2] : 0.f, a3 = ok1 ? acc[nt][3] : 0.f;
        float se = a0 + a2, so = a1 + a3;
        float qe = a0 * a0 + a2 * a2, qo = a1 * a1 + a3 * a3;
#pragma unroll
        for (int off = 16; off >= 4; off >>= 1) {
            se += __shfl_down_sync(0xffffffffu, se, off);
            so += __shfl_down_sync(0xffffffffu, so, off);
            qe += __shfl_down_sync(0xffffffffu, qe, off);
            qo += __shfl_down_sync(0xffffffffu, qo, off);
        }
        if (lane < 4) {
            atomicAdd(&s_sum[col], se);
            atomicAdd(&s_sum[col + 1], so);
            atomicAdd(&s_sq[col], qe);
            atomicAdd(&s_sq[col + 1], qo);
        }
    }
    __syncthreads();
    if (tid < D) {
        atomicAdd(&sums[tid], s_sum[tid]);
        atomicAdd(&sumsq[tid], s_sq[tid]);
    }
}

// ================= bn+tanh -> fp16 x table =================
__global__ void k_bntanh(const float* __restrict__ xin) {
    int i = blockIdx.x * blockDim.x + threadIdx.x;
    if (i >= N_ENT * D / 4) return;
    int c4 = (i & 31) * 4;
    float4 v = reinterpret_cast<const float4*>(xin)[i];
    float x = tanhf(v.x * g_scale[c4 + 0] + g_shift[c4 + 0]);
    float y = tanhf(v.y * g_scale[c4 + 1] + g_shift[c4 + 1]);
    float z = tanhf(v.z * g_scale[c4 + 2] + g_shift[c4 + 2]);
    float w = tanhf(v.w * g_scale[c4 + 3] + g_shift[c4 + 3]);
    reinterpret_cast<uint2*>(g_xh)[i] = make_uint2(pkh(x, y), pkh(z, w));
}

// ================= scoring (layer-2 BN+tanh fused) =================
__global__ void k_score(const int* __restrict__ trip, float* __restrict__ out) {
    int t = blockIdx.x * 8 + (threadIdx.x >> 5);
    if (t >= N_TRIPLES_C) return;
    int lane = threadIdx.x & 31;
    int h = trip[t * 3], rl = trip[t * 3 + 1], tl = trip[t * 3 + 2];
    float4 sc = *(reinterpret_cast<const float4*>(g_scale) + lane);
    float4 sh = *(reinterpret_cast<const float4*>(g_shift) + lane);
    float4 hv = *(reinterpret_cast<const float4*>(g_X2 + (size_t)h * D) + lane);
    float4 rv = *(reinterpret_cast<const float4*>(g_r2 + (size_t)rl * D) + lane);
    float4 tv = *(reinterpret_cast<const float4*>(g_X2 + (size_t)tl * D) + lane);
    float hx = tanhf(hv.x * sc.x + sh.x), tx = tanhf(tv.x * sc.x + sh.x);
    float hy = tanhf(hv.y * sc.y + sh.y), ty = tanhf(tv.y * sc.y + sh.y);
    float hz = tanhf(hv.z * sc.z + sh.z), tz = tanhf(tv.z * sc.z + sh.z);
    float hw = tanhf(hv.w * sc.w + sh.w), tw = tanhf(tv.w * sc.w + sh.w);
    float p = fabsf(hx + rv.x - tx) + fabsf(hy + rv.y - ty) +
              fabsf(hz + rv.z - tz) + fabsf(hw + rv.w - tw);
#pragma unroll
    for (int o = 16; o; o >>= 1) p += __shfl_xor_sync(0xffffffffu, p, o);
    if (lane == 0) out[t] = p;
}

// ================= host side =================
static float* sym_addr_f(const void* sym) {
    void* p = nullptr;
    cudaGetSymbolAddress(&p, sym);
    return reinterpret_cast<float*>(p);
}

extern "C" void kernel_launch(void* const* d_in, const int* in_sizes, int n_in,
                              void* d_out, int out_size) {
    (void)in_sizes; (void)n_in; (void)out_size;
    const float* entity = (const float*)d_in[0];
    const float* bases  = (const float*)d_in[1];
    const float* coeff  = (const float*)d_in[2];
    const float* selfr  = (const float*)d_in[3];
    const float* W1     = (const float*)d_in[4];
    const float* relw1  = (const float*)d_in[5];
    const float* g1     = (const float*)d_in[6];
    const float* b1     = (const float*)d_in[7];
    const float* W2     = (const float*)d_in[8];
    const float* relw2  = (const float*)d_in[9];
    const float* g2     = (const float*)d_in[10];
    const float* b2     = (const float*)d_in[11];
    const int* edge_index = (const int*)d_in[13];
    const int* edge_type  = (const int*)d_in[14];
    const int* yv         = (const int*)d_in[15];
    const int* triples    = (const int*)d_in[16];
    float* out = (float*)d_out;

    float* p_r0 = sym_addr_f(g_r0);
    float* p_r1 = sym_addr_f(g_r1);
    float* p_r2 = sym_addr_f(g_r2);
    float* p_X1 = sym_addr_f(g_X1);
    float* p_X2 = sym_addr_f(g_X2);
    float* p_sums = sym_addr_f(g_sums);
    float* p_sumsq = sym_addr_f(g_sumsq);
    __half* p_rh = nullptr;
    {
        void* q = nullptr;
        cudaGetSymbolAddress(&q, g_rh);
        p_rh = reinterpret_cast<__half*>(q);
    }
    __half* p_Wh = nullptr;
    {
        void* q = nullptr;
        cudaGetSymbolAddress(&q, g_Wh);
        p_Wh = reinterpret_cast<__half*>(q);
    }

    cudaFuncSetAttribute(k_gemm, cudaFuncAttributeMaxDynamicSharedMemorySize, SMEM_DYN);

    // ---- prep: r0 + deg zero, entity fp16, W fp16 (both layers), CSR ----
    k_r0z<<<201 + (N_ENT + 255) / 256, 256>>>(coeff, bases, selfr);
    k_xconv<<<(N_ENT * D / 4 + 255) / 256, 256>>>(entity);
    k_wsplit2<<<6, 256>>>(W1, W2);
    k_hist<<<(N_EDGES_C + 255) / 256, 256>>>(edge_index);
    k_scan1<<<SCAN_BLKS, 256>>>();
    k_scan3<<<(N_ENT + 255) / 256, 256>>>();
    k_perm<<<(N_EDGES_C + 255) / 256, 256>>>(edge_index, edge_type, yv);

    // ---- layer 1 ----
    k_aggr<<<N_ENT / 8, 256>>>();
    k_gemm<<<GEMM_BLKS, 256, SMEM_DYN>>>(p_X1, p_Wh, p_sums, p_sumsq);
    k_rel<<<N_RELS + 1, 128>>>(p_r0, relw1, p_r1, p_rh, g1, b1, p_sums, p_sumsq);
    k_bntanh<<<N_ENT * D / 4 / 256, 256>>>(p_X1);

    // ---- layer 2 ----
    k_aggr<<<N_ENT / 8, 256>>>();
    k_gemm<<<GEMM_BLKS, 256, SMEM_DYN>>>(p_X2, p_Wh + 3 * D * D, p_sums + D, p_sumsq + D);
    k_rel<<<N_RELS + 1, 128>>>(p_r1, relw2, p_r2, nullptr, g2, b2, p_sums + D, p_sumsq + D);

    // ---- scoring (applies layer-2 BN+tanh on the fly) ----
    k_score<<<N_TRIPLES_C / 8, 256>>>(triples, out);
}